// round 12
// baseline (speedup 1.0000x reference)
#include <cuda_runtime.h>
#include <cuda_bf16.h>
#include <cstdint>
#include <stdint.h>
#include <math.h>

#define MAX_N 50000
#define MAX_E 400000
#define MAX_ETOT (MAX_N + MAX_E)
#define NEG_SLOPE 0.2f
#define NPAD (MAX_N + 128)

// ---------------- scratch (device globals, allocation-free) ----------------
__device__ float g_h1[MAX_N * 256];    // conv1 features  [N,2,128]
__device__ float g_h2[MAX_N * 128];    // layer2 feats    [N,{mu,ls},64]
__device__ float g_asrc1[MAX_N * 2];
__device__ float g_adst1[MAX_N * 2];
__device__ float g_asrc2[MAX_N * 2];
__device__ float g_adst2[MAX_N * 2];
__device__ int   g_deg[MAX_N];
__device__ int   g_off[MAX_N + 1];
__device__ int   g_cur[MAX_N];
__device__ int   g_csr[MAX_ETOT];      // src node per CSR slot (sorted by dst)

// bf16 hi/lo operand arrays (zero-initialized; padding rows stay 0)
__device__ __nv_bfloat16 g_xhi[NPAD * 128],  g_xlo[NPAD * 128];   // layer1 A
__device__ __nv_bfloat16 g_a2hi[NPAD * 256], g_a2lo[NPAD * 256];  // layer2 A (ELU out)
__device__ __nv_bfloat16 g_w1hi[256 * 128],  g_w1lo[256 * 128];   // layer1 B  [n][k]
__device__ __nv_bfloat16 g_w2hi[128 * 256],  g_w2lo[128 * 256];   // layer2 B  [n][k]

// ======================= PTX helpers ======================================
__device__ __forceinline__ uint32_t smem_u32(const void* p) {
    uint32_t a;
    asm("{ .reg .u64 t; cvta.to.shared.u64 t, %1; cvt.u32.u64 %0, t; }"
        : "=r"(a) : "l"(p));
    return a;
}

#define CP16(saddr, gptr) \
    asm volatile("cp.async.cg.shared.global [%0], [%1], 16;" \
                 :: "r"(saddr), "l"(gptr) : "memory")
#define CP_COMMIT() asm volatile("cp.async.commit_group;" ::: "memory")
#define CP_WAIT0()  asm volatile("cp.async.wait_group 0;" ::: "memory")
#define CP_WAIT1()  asm volatile("cp.async.wait_group 1;" ::: "memory")

#define LDSM4(r0, r1, r2, r3, addr)                                            \
    asm volatile("ldmatrix.sync.aligned.m8n8.x4.shared.b16 {%0,%1,%2,%3}, [%4];" \
                 : "=r"(r0), "=r"(r1), "=r"(r2), "=r"(r3) : "r"(addr))

#define MMA_OP(c, a, b)                                                        \
    asm volatile(                                                              \
        "mma.sync.aligned.m16n8k16.row.col.f32.bf16.bf16.f32 "                 \
        "{%0,%1,%2,%3}, {%4,%5,%6,%7}, {%8,%9}, {%0,%1,%2,%3};"                \
        : "+f"((c)[0]), "+f"((c)[1]), "+f"((c)[2]), "+f"((c)[3])               \
        : "r"((a)[0]), "r"((a)[1]), "r"((a)[2]), "r"((a)[3]),                  \
          "r"((b)[0]), "r"((b)[1]))

// smem tile geometry: 128 rows x 32 k, row stride 40 bf16 (80 B, LDSM-clean)
#define TROW 40
#define TELEM (128 * TROW)
#define STAGE_ELEM (4 * TELEM)
#define GEMM_SMEM (2 * STAGE_ELEM * 2)

// ===========================================================================
// bf16 hi/lo split GEMM + fused attention-scalar epilogue
// ===========================================================================
__global__ __launch_bounds__(256) void gemm_bf16_kernel(
    const __nv_bfloat16* __restrict__ Ahi, const __nv_bfloat16* __restrict__ Alo,
    const __nv_bfloat16* __restrict__ Bhi, const __nv_bfloat16* __restrict__ Blo,
    float* __restrict__ C, int M, int KTOT, int ldc,
    const float* __restrict__ attS0, const float* __restrict__ attS1,
    const float* __restrict__ attD0, const float* __restrict__ attD1,
    int hshift, float* __restrict__ asrc, float* __restrict__ adst)
{
    extern __shared__ __nv_bfloat16 sm[];
    const uint32_t sbase = smem_u32(sm);

    const int tid = threadIdx.x, warp = tid >> 5, lane = tid & 31;
    const int wm = warp & 1, wn = warp >> 1;
    const int row0 = blockIdx.y * 128;
    const int col0 = blockIdx.x * 128;
    const int nch = KTOT >> 5;

    float acc[4][4][4];
#pragma unroll
    for (int mt = 0; mt < 4; mt++)
#pragma unroll
        for (int nt = 0; nt < 4; nt++)
#pragma unroll
            for (int i = 0; i < 4; i++) acc[mt][nt][i] = 0.f;

    auto issue = [&](int stage, int kb) {
        const int so = stage * STAGE_ELEM;
#pragma unroll
        for (int it = 0; it < 2; it++) {
            int vec = tid + it * 256;
            int m = vec >> 2, ko = (vec & 3) * 8;
            uint32_t sd = sbase + (uint32_t)(so + m * TROW + ko) * 2;
            size_t ga = (size_t)(row0 + m) * KTOT + kb + ko;
            CP16(sd,             Ahi + ga);
            CP16(sd + TELEM * 2, Alo + ga);
            size_t gb = (size_t)(col0 + m) * KTOT + kb + ko;
            CP16(sd + TELEM * 4, Bhi + gb);
            CP16(sd + TELEM * 6, Blo + gb);
        }
        CP_COMMIT();
    };

    issue(0, 0);

    const int arow = wm * 64 + (lane & 15);
    const int acol = (lane >> 4) * 8;
    const int bmid = lane >> 3, brin = lane & 7;

    for (int c = 0; c < nch; c++) {
        if (c + 1 < nch) { issue((c + 1) & 1, (c + 1) * 32); CP_WAIT1(); }
        else             { CP_WAIT0(); }
        __syncthreads();

        const uint32_t aAh = sbase + (uint32_t)((c & 1) * STAGE_ELEM) * 2;
        const uint32_t aAl = aAh + TELEM * 2;
        const uint32_t aBh = aAh + TELEM * 4;
        const uint32_t aBl = aAh + TELEM * 6;

#pragma unroll
        for (int ks = 0; ks < 2; ks++) {
            const int k0 = ks * 16;
            uint32_t ah[4][4], al[4][4];
#pragma unroll
            for (int mt = 0; mt < 4; mt++) {
                uint32_t off = (uint32_t)((arow + mt * 16) * TROW + k0 + acol) * 2;
                LDSM4(ah[mt][0], ah[mt][1], ah[mt][2], ah[mt][3], aAh + off);
                LDSM4(al[mt][0], al[mt][1], al[mt][2], al[mt][3], aAl + off);
            }
            uint32_t bh[4][2], bl[4][2];
#pragma unroll
            for (int p = 0; p < 2; p++) {
                int bn = wn * 32 + p * 16 + (bmid >> 1) * 8 + brin;
                int bc = k0 + (bmid & 1) * 8;
                uint32_t off = (uint32_t)(bn * TROW + bc) * 2;
                uint32_t r0, r1, r2, r3;
                LDSM4(r0, r1, r2, r3, aBh + off);
                bh[p * 2][0] = r0; bh[p * 2][1] = r1;
                bh[p * 2 + 1][0] = r2; bh[p * 2 + 1][1] = r3;
                LDSM4(r0, r1, r2, r3, aBl + off);
                bl[p * 2][0] = r0; bl[p * 2][1] = r1;
                bl[p * 2 + 1][0] = r2; bl[p * 2 + 1][1] = r3;
            }
#pragma unroll
            for (int mt = 0; mt < 4; mt++)
#pragma unroll
                for (int nt = 0; nt < 4; nt++) {
                    MMA_OP(acc[mt][nt], ah[mt], bh[nt]);
                    MMA_OP(acc[mt][nt], ah[mt], bl[nt]);
                    MMA_OP(acc[mt][nt], al[mt], bh[nt]);
                }
        }
        __syncthreads();
    }

    const int qrow = lane >> 2, qcol = (lane & 3) * 2;

#pragma unroll
    for (int mt = 0; mt < 4; mt++) {
#pragma unroll
        for (int nt = 0; nt < 4; nt++) {
            int r = row0 + wm * 64 + mt * 16 + qrow;
            int cc = col0 + wn * 32 + nt * 8 + qcol;
            if (r < M)
                *(float2*)&C[(size_t)r * ldc + cc] =
                    make_float2(acc[mt][nt][0], acc[mt][nt][1]);
            if (r + 8 < M)
                *(float2*)&C[(size_t)(r + 8) * ldc + cc] =
                    make_float2(acc[mt][nt][2], acc[mt][nt][3]);
        }
    }

    // ---- fused attention scalars
    const int hmask = (1 << hshift) - 1;
    const int h = (col0 + wn * 32) >> hshift;
    const float* aS = h ? attS1 : attS0;
    const float* aD = h ? attD1 : attD0;
    float ws[4][2], wd[4][2];
#pragma unroll
    for (int nt = 0; nt < 4; nt++) {
        int ci = (col0 + wn * 32 + nt * 8 + qcol) & hmask;
        ws[nt][0] = aS[ci];     ws[nt][1] = aS[ci + 1];
        wd[nt][0] = aD[ci];     wd[nt][1] = aD[ci + 1];
    }
#pragma unroll
    for (int mt = 0; mt < 4; mt++) {
        float slo = 0.f, shi = 0.f, dlo = 0.f, dhi = 0.f;
#pragma unroll
        for (int nt = 0; nt < 4; nt++) {
            slo += acc[mt][nt][0] * ws[nt][0] + acc[mt][nt][1] * ws[nt][1];
            shi += acc[mt][nt][2] * ws[nt][0] + acc[mt][nt][3] * ws[nt][1];
            dlo += acc[mt][nt][0] * wd[nt][0] + acc[mt][nt][1] * wd[nt][1];
            dhi += acc[mt][nt][2] * wd[nt][0] + acc[mt][nt][3] * wd[nt][1];
        }
#pragma unroll
        for (int o = 1; o <= 2; o <<= 1) {
            slo += __shfl_xor_sync(~0u, slo, o);
            shi += __shfl_xor_sync(~0u, shi, o);
            dlo += __shfl_xor_sync(~0u, dlo, o);
            dhi += __shfl_xor_sync(~0u, dhi, o);
        }
        if ((lane & 3) == 0) {
            int r = row0 + wm * 64 + mt * 16 + qrow;
            if (r < M) {
                atomicAdd(&asrc[r * 2 + h], slo);
                atomicAdd(&adst[r * 2 + h], dlo);
            }
            if (r + 8 < M) {
                atomicAdd(&asrc[(r + 8) * 2 + h], shi);
                atomicAdd(&adst[(r + 8) * 2 + h], dhi);
            }
        }
    }
}

// ---------------------------------------------------------------------------
__global__ void zero_all_kernel(int* __restrict__ deg,
                                float* __restrict__ a1, float* __restrict__ d1,
                                float* __restrict__ a2, float* __restrict__ d2,
                                int N)
{
    int i = blockIdx.x * blockDim.x + threadIdx.x;
    if (i >= N) return;
    deg[i] = 0;
    float2 z = make_float2(0.f, 0.f);
    *(float2*)&a1[i * 2] = z;
    *(float2*)&d1[i * 2] = z;
    *(float2*)&a2[i * 2] = z;
    *(float2*)&d2[i * 2] = z;
}

// ---------------------------------------------------------------------------
// fused: hi/lo conversion (x, W1T, W2T) + edge histogram (independent work,
// both depend only on inputs and the zero pass)
// ---------------------------------------------------------------------------
__global__ void cvt_hist_kernel(const float* __restrict__ x,
                                const float* __restrict__ W1,
                                const float* __restrict__ Wmu,
                                const float* __restrict__ Wls,
                                __nv_bfloat16* __restrict__ xhi,
                                __nv_bfloat16* __restrict__ xlo,
                                __nv_bfloat16* __restrict__ w1hi,
                                __nv_bfloat16* __restrict__ w1lo,
                                __nv_bfloat16* __restrict__ w2hi,
                                __nv_bfloat16* __restrict__ w2lo,
                                int nx,
                                const int* __restrict__ ei, int nE, int nTot,
                                int* __restrict__ deg)
{
    int i = blockIdx.x * blockDim.x + threadIdx.x;
    const int ncvt = nx + 256 * 128 + 128 * 256;
    if (i < ncvt) {
        float v;
        __nv_bfloat16* hi;
        __nv_bfloat16* lo;
        int o;
        if (i < nx) {
            v = x[i]; hi = xhi; lo = xlo; o = i;
        } else if (i < nx + 256 * 128) {
            o = i - nx;
            int n = o >> 7, k = o & 127;
            v = W1[k * 256 + n]; hi = w1hi; lo = w1lo;
        } else {
            o = i - nx - 256 * 128;
            int n = o >> 8, k = o & 255;
            v = (n < 64) ? Wmu[k * 64 + n] : Wls[k * 64 + n - 64];
            hi = w2hi; lo = w2lo;
        }
        __nv_bfloat16 h = __float2bfloat16(v);
        hi[o] = h;
        lo[o] = __float2bfloat16(v - __bfloat162float(h));
    } else {
        int e = i - ncvt;
        if (e < nTot) {
            int d = (e < nE) ? ei[nE + e] : e - nE;
            atomicAdd(&deg[d], 1);
        }
    }
}

// ---------------------------------------------------------------------------
// CSR build (scan + scatter)
// ---------------------------------------------------------------------------
__global__ __launch_bounds__(1024) void scan_kernel(
    const int* __restrict__ deg, int* __restrict__ off,
    int* __restrict__ cur, int N)
{
    __shared__ int ssum[1024];
    int tid = threadIdx.x;
    int chunk = (N + 1023) / 1024;
    int start = tid * chunk;
    int end = min(start + chunk, N);
    int s = 0;
    for (int i = start; i < end; i++) s += deg[i];
    ssum[tid] = s;
    __syncthreads();
    for (int o = 1; o < 1024; o <<= 1) {
        int v = 0;
        if (tid >= o) v = ssum[tid - o];
        __syncthreads();
        if (tid >= o) ssum[tid] += v;
        __syncthreads();
    }
    int base = (tid > 0) ? ssum[tid - 1] : 0;
    for (int i = start; i < end; i++) {
        off[i] = base;
        cur[i] = base;
        base += deg[i];
    }
    if (tid == 1023) off[N] = ssum[1023];
}

__global__ void scatter_kernel(const int* __restrict__ ei, int nE, int nTot,
                               int* __restrict__ cur, int* __restrict__ csr)
{
    int e = blockIdx.x * blockDim.x + threadIdx.x;
    if (e >= nTot) return;
    int s, d;
    if (e < nE) { s = ei[e]; d = ei[nE + e]; }
    else        { s = e - nE; d = s; }
    int pos = atomicAdd(&cur[d], 1);
    csr[pos] = s;
}

// ---------------------------------------------------------------------------
__device__ __forceinline__ float lrelu(float v) { return v > 0.f ? v : NEG_SLOPE * v; }

// ---------------------------------------------------------------------------
// layer-1 agg: warp per node, both heads; online softmax; 2-edge x 2-head gather
// ---------------------------------------------------------------------------
__global__ void agg1_kernel(const int* __restrict__ off, const int* __restrict__ csr,
                            const float* __restrict__ asrc, const float* __restrict__ adst,
                            const float* __restrict__ feat, const float* __restrict__ bias,
                            __nv_bfloat16* __restrict__ ohi,
                            __nv_bfloat16* __restrict__ olo, int Nn)
{
    int warpi = (blockIdx.x * blockDim.x + threadIdx.x) >> 5;
    int lane = threadIdx.x & 31;
    if (warpi >= Nn) return;
    int n = warpi;
    int o0 = off[n], o1 = off[n + 1];
    float2 adv = *(const float2*)&adst[n * 2];

    float m0 = -1e30f, d0 = 0.f, m1 = -1e30f, d1 = 0.f;
    for (int j = o0 + lane; j < o1; j += 32) {
        float2 a = *(const float2*)&asrc[csr[j] * 2];
        float e0 = lrelu(a.x + adv.x);
        float e1 = lrelu(a.y + adv.y);
        float nm0 = fmaxf(m0, e0);
        d0 = d0 * __expf(m0 - nm0) + __expf(e0 - nm0);
        m0 = nm0;
        float nm1 = fmaxf(m1, e1);
        d1 = d1 * __expf(m1 - nm1) + __expf(e1 - nm1);
        m1 = nm1;
    }
#pragma unroll
    for (int o = 16; o; o >>= 1) {
        float mo = __shfl_xor_sync(~0u, m0, o), dd = __shfl_xor_sync(~0u, d0, o);
        float nm = fmaxf(m0, mo);
        d0 = d0 * __expf(m0 - nm) + dd * __expf(mo - nm);
        m0 = nm;
        mo = __shfl_xor_sync(~0u, m1, o); dd = __shfl_xor_sync(~0u, d1, o);
        nm = fmaxf(m1, mo);
        d1 = d1 * __expf(m1 - nm) + dd * __expf(mo - nm);
        m1 = nm;
    }
    float inv0 = 1.f / (d0 + 1e-16f);
    float inv1 = 1.f / (d1 + 1e-16f);

    const float* f0 = feat + lane * 4;
    const float* f1 = feat + 128 + lane * 4;
    float4 acc0 = make_float4(0.f, 0.f, 0.f, 0.f);
    float4 acc1 = make_float4(0.f, 0.f, 0.f, 0.f);
    int j = o0;
    for (; j + 1 < o1; j += 2) {
        int s0 = csr[j], s1 = csr[j + 1];
        float2 a0 = *(const float2*)&asrc[s0 * 2];
        float2 a1 = *(const float2*)&asrc[s1 * 2];
        float w00 = __expf(lrelu(a0.x + adv.x) - m0) * inv0;
        float w01 = __expf(lrelu(a0.y + adv.y) - m1) * inv1;
        float w10 = __expf(lrelu(a1.x + adv.x) - m0) * inv0;
        float w11 = __expf(lrelu(a1.y + adv.y) - m1) * inv1;
        float4 p00 = *(const float4*)(f0 + (size_t)s0 * 256);
        float4 p01 = *(const float4*)(f1 + (size_t)s0 * 256);
        float4 p10 = *(const float4*)(f0 + (size_t)s1 * 256);
        float4 p11 = *(const float4*)(f1 + (size_t)s1 * 256);
        acc0.x += w00 * p00.x + w10 * p10.x;
        acc0.y += w00 * p00.y + w10 * p10.y;
        acc0.z += w00 * p00.z + w10 * p10.z;
        acc0.w += w00 * p00.w + w10 * p10.w;
        acc1.x += w01 * p01.x + w11 * p11.x;
        acc1.y += w01 * p01.y + w11 * p11.y;
        acc1.z += w01 * p01.z + w11 * p11.z;
        acc1.w += w01 * p01.w + w11 * p11.w;
    }
    for (; j < o1; j++) {
        int s = csr[j];
        float2 a = *(const float2*)&asrc[s * 2];
        float w0 = __expf(lrelu(a.x + adv.x) - m0) * inv0;
        float w1 = __expf(lrelu(a.y + adv.y) - m1) * inv1;
        float4 p0 = *(const float4*)(f0 + (size_t)s * 256);
        float4 p1 = *(const float4*)(f1 + (size_t)s * 256);
        acc0.x += w0 * p0.x; acc0.y += w0 * p0.y;
        acc0.z += w0 * p0.z; acc0.w += w0 * p0.w;
        acc1.x += w1 * p1.x; acc1.y += w1 * p1.y;
        acc1.z += w1 * p1.z; acc1.w += w1 * p1.w;
    }

    float4 b0 = *(const float4*)(bias + lane * 4);
    float4 b1 = *(const float4*)(bias + 128 + lane * 4);
    float vv0[4] = {acc0.x + b0.x, acc0.y + b0.y, acc0.z + b0.z, acc0.w + b0.w};
    float vv1[4] = {acc1.x + b1.x, acc1.y + b1.y, acc1.z + b1.z, acc1.w + b1.w};
    ushort4 hv0, lv0, hv1, lv1;
    unsigned short *hp0 = &hv0.x, *lp0 = &lv0.x, *hp1 = &hv1.x, *lp1 = &lv1.x;
#pragma unroll
    for (int q = 0; q < 4; q++) {
        float e0 = vv0[q] > 0.f ? vv0[q] : expm1f(vv0[q]);
        __nv_bfloat16 hb = __float2bfloat16(e0);
        hp0[q] = __bfloat16_as_ushort(hb);
        lp0[q] = __bfloat16_as_ushort(__float2bfloat16(e0 - __bfloat162float(hb)));
        float e1 = vv1[q] > 0.f ? vv1[q] : expm1f(vv1[q]);
        hb = __float2bfloat16(e1);
        hp1[q] = __bfloat16_as_ushort(hb);
        lp1[q] = __bfloat16_as_ushort(__float2bfloat16(e1 - __bfloat162float(hb)));
    }
    size_t idx = (size_t)n * 256 + lane * 4;
    *(ushort4*)&ohi[idx] = hv0;
    *(ushort4*)&olo[idx] = lv0;
    *(ushort4*)&ohi[idx + 128] = hv1;
    *(ushort4*)&olo[idx + 128] = lv1;
}

// ---------------------------------------------------------------------------
// layer-2 agg: warp per node, heads on half-warps, online softmax stats
// ---------------------------------------------------------------------------
__global__ void agg2_kernel(const int* __restrict__ off, const int* __restrict__ csr,
                            const float* __restrict__ asrc, const float* __restrict__ adst,
                            const float* __restrict__ feat,
                            const float* __restrict__ bmu, const float* __restrict__ bls,
                            float* __restrict__ out, long headStride, int Nn)
{
    int warpi = (blockIdx.x * blockDim.x + threadIdx.x) >> 5;
    int lane = threadIdx.x & 31;
    if (warpi >= Nn) return;
    int n = warpi;
    int h = lane >> 4, l = lane & 15;
    int o0 = off[n], o1 = off[n + 1];
    float ad = adst[n * 2 + h];

    float m = -1e30f, den = 0.f;
    for (int j = o0 + l; j < o1; j += 16) {
        float e = lrelu(asrc[csr[j] * 2 + h] + ad);
        float nm = fmaxf(m, e);
        den = den * __expf(m - nm) + __expf(e - nm);
        m = nm;
    }
#pragma unroll
    for (int o = 8; o; o >>= 1) {
        float mo = __shfl_xor_sync(~0u, m, o), dd = __shfl_xor_sync(~0u, den, o);
        float nm = fmaxf(m, mo);
        den = den * __expf(m - nm) + dd * __expf(mo - nm);
        m = nm;
    }
    float inv = 1.f / (den + 1e-16f);

    float4 acc = make_float4(0.f, 0.f, 0.f, 0.f);
    const float* fb = feat + h * 64 + l * 4;
    int j = o0;
    for (; j + 3 < o1; j += 4) {
        int s0 = csr[j], s1 = csr[j + 1], s2 = csr[j + 2], s3 = csr[j + 3];
        float a0 = __expf(lrelu(asrc[s0 * 2 + h] + ad) - m) * inv;
        float a1 = __expf(lrelu(asrc[s1 * 2 + h] + ad) - m) * inv;
        float a2 = __expf(lrelu(asrc[s2 * 2 + h] + ad) - m) * inv;
        float a3 = __expf(lrelu(asrc[s3 * 2 + h] + ad) - m) * inv;
        float4 p0 = *(const float4*)(fb + (size_t)s0 * 128);
        float4 p1 = *(const float4*)(fb + (size_t)s1 * 128);
        float4 p2 = *(const float4*)(fb + (size_t)s2 * 128);
        float4 p3 = *(const float4*)(fb + (size_t)s3 * 128);
        acc.x += a0 * p0.x + a1 * p1.x + a2 * p2.x + a3 * p3.x;
        acc.y += a0 * p0.y + a1 * p1.y + a2 * p2.y + a3 * p3.y;
        acc.z += a0 * p0.z + a1 * p1.z + a2 * p2.z + a3 * p3.z;
        acc.w += a0 * p0.w + a1 * p1.w + a2 * p2.w + a3 * p3.w;
    }
    for (; j < o1; j++) {
        int s = csr[j];
        float a = __expf(lrelu(asrc[s * 2 + h] + ad) - m) * inv;
        float4 p = *(const float4*)(fb + (size_t)s * 128);
        acc.x += a * p.x; acc.y += a * p.y; acc.z += a * p.z; acc.w += a * p.w;
    }

    float4 b4 = *(const float4*)((h ? bls : bmu) + l * 4);
    acc.x += b4.x; acc.y += b4.y; acc.z += b4.z; acc.w += b4.w;
    *(float4*)&out[(size_t)h * headStride + (size_t)n * 64 + l * 4] = acc;
}

// ---------------------------------------------------------------------------
static inline int cdiv(long a, int b) { return (int)((a + b - 1) / b); }

extern "C" void kernel_launch(void* const* d_in, const int* in_sizes, int n_in,
                              void* d_out, int out_size)
{
    const float* x          = (const float*)d_in[0];
    const int*   edge_index = (const int*)d_in[1];
    const float* W1         = (const float*)d_in[2];
    const float* att_src1   = (const float*)d_in[3];
    const float* att_dst1   = (const float*)d_in[4];
    const float* b1         = (const float*)d_in[5];
    const float* W_mu       = (const float*)d_in[6];
    const float* att_src_mu = (const float*)d_in[7];
    const float* att_dst_mu = (const float*)d_in[8];
    const float* b_mu       = (const float*)d_in[9];
    const float* W_ls       = (const float*)d_in[10];
    const float* att_src_ls = (const float*)d_in[11];
    const float* att_dst_ls = (const float*)d_in[12];
    const float* b_ls       = (const float*)d_in[13];
    float* out = (float*)d_out;

    const int N  = in_sizes[0] / 128;
    const int nE = in_sizes[1] / 2;
    const int nTot = nE + N;

    float *p_h1, *p_h2, *p_as1, *p_ad1, *p_as2, *p_ad2;
    int *p_deg, *p_off, *p_cur, *p_csr;
    __nv_bfloat16 *p_xhi, *p_xlo, *p_a2hi, *p_a2lo, *p_w1hi, *p_w1lo, *p_w2hi, *p_w2lo;
    cudaGetSymbolAddress((void**)&p_h1,   g_h1);
    cudaGetSymbolAddress((void**)&p_h2,   g_h2);
    cudaGetSymbolAddress((void**)&p_as1,  g_asrc1);
    cudaGetSymbolAddress((void**)&p_ad1,  g_adst1);
    cudaGetSymbolAddress((void**)&p_as2,  g_asrc2);
    cudaGetSymbolAddress((void**)&p_ad2,  g_adst2);
    cudaGetSymbolAddress((void**)&p_deg,  g_deg);
    cudaGetSymbolAddress((void**)&p_off,  g_off);
    cudaGetSymbolAddress((void**)&p_cur,  g_cur);
    cudaGetSymbolAddress((void**)&p_csr,  g_csr);
    cudaGetSymbolAddress((void**)&p_xhi,  g_xhi);
    cudaGetSymbolAddress((void**)&p_xlo,  g_xlo);
    cudaGetSymbolAddress((void**)&p_a2hi, g_a2hi);
    cudaGetSymbolAddress((void**)&p_a2lo, g_a2lo);
    cudaGetSymbolAddress((void**)&p_w1hi, g_w1hi);
    cudaGetSymbolAddress((void**)&p_w1lo, g_w1lo);
    cudaGetSymbolAddress((void**)&p_w2hi, g_w2hi);
    cudaGetSymbolAddress((void**)&p_w2lo, g_w2lo);

    cudaFuncSetAttribute(gemm_bf16_kernel,
                         cudaFuncAttributeMaxDynamicSharedMemorySize, GEMM_SMEM);

    const int T = 256;

    // 1) zero deg + att-scalar buffers
    zero_all_kernel<<<cdiv(N, T), T>>>(p_deg, p_as1, p_ad1, p_as2, p_ad2, N);
    // 2) fused hi/lo conversion + edge histogram
    {
        long total = (long)N * 128 + 256 * 128 + 128 * 256 + nTot;
        cvt_hist_kernel<<<cdiv(total, T), T>>>(x, W1, W_mu, W_ls,
            p_xhi, p_xlo, p_w1hi, p_w1lo, p_w2hi, p_w2lo, N * 128,
            edge_index, nE, nTot, p_deg);
    }
    // 3-4) CSR scan + scatter
    scan_kernel<<<1, 1024>>>(p_deg, p_off, p_cur, N);
    scatter_kernel<<<cdiv(nTot, T), T>>>(edge_index, nE, nTot, p_cur, p_csr);
    // 5) layer-1 GEMM + fused att scalars
    {
        dim3 grid(2, cdiv(N, 128));
        gemm_bf16_kernel<<<grid, 256, GEMM_SMEM>>>(
            p_xhi, p_xlo, p_w1hi, p_w1lo, p_h1, N, 128, 256,
            att_src1, att_src1 + 128, att_dst1, att_dst1 + 128, 7, p_as1, p_ad1);
    }
    // 6) layer-1 aggregation
    agg1_kernel<<<cdiv((long)N * 32, T), T>>>(
        p_off, p_csr, p_as1, p_ad1, p_h1, b1, p_a2hi, p_a2lo, N);
    // 7) layer-2 GEMM + fused att scalars
    {
        dim3 grid(1, cdiv(N, 128));
        gemm_bf16_kernel<<<grid, 256, GEMM_SMEM>>>(
            p_a2hi, p_a2lo, p_w2hi, p_w2lo, p_h2, N, 256, 128,
            att_src_mu, att_src_ls, att_dst_mu, att_dst_ls, 6, p_as2, p_ad2);
    }
    // 8) layer-2 aggregation -> output
    agg2_kernel<<<cdiv((long)N * 32, T), T>>>(
        p_off, p_csr, p_as2, p_ad2, p_h2, b_mu, b_ls, out, (long)N * 64, N);
}

// round 13
// speedup vs baseline: 1.5087x; 1.5087x over previous
#include <cuda_runtime.h>
#include <cuda_bf16.h>
#include <cstdint>
#include <stdint.h>
#include <math.h>

#define MAX_N 50000
#define MAX_E 400000
#define MAX_ETOT (MAX_N + MAX_E)
#define NEG_SLOPE 0.2f
#define NPAD (MAX_N + 128)

// ---------------- scratch (device globals, allocation-free) ----------------
__device__ float g_h1[MAX_N * 256];    // conv1 features  [N,2,128]
__device__ float g_h2[MAX_N * 128];    // layer2 feats    [N,{mu,ls},64]
__device__ float g_asrc1[MAX_N * 2];
__device__ float g_adst1[MAX_N * 2];
__device__ float g_asrc2[MAX_N * 2];
__device__ float g_adst2[MAX_N * 2];
__device__ int   g_deg[MAX_N];
__device__ int   g_off[MAX_N + 1];
__device__ int   g_cur[MAX_N];
__device__ int   g_csr[MAX_ETOT];      // src node per CSR slot (sorted by dst)

// bf16 hi/lo operand arrays (zero-initialized; padding rows stay 0)
__device__ __nv_bfloat16 g_xhi[NPAD * 128],  g_xlo[NPAD * 128];   // layer1 A
__device__ __nv_bfloat16 g_a2hi[NPAD * 256], g_a2lo[NPAD * 256];  // layer2 A (ELU out)
__device__ __nv_bfloat16 g_w1hi[256 * 128],  g_w1lo[256 * 128];   // layer1 B  [n][k]
__device__ __nv_bfloat16 g_w2hi[128 * 256],  g_w2lo[128 * 256];   // layer2 B  [n][k]

// ======================= PTX helpers ======================================
__device__ __forceinline__ uint32_t smem_u32(const void* p) {
    uint32_t a;
    asm("{ .reg .u64 t; cvta.to.shared.u64 t, %1; cvt.u32.u64 %0, t; }"
        : "=r"(a) : "l"(p));
    return a;
}

#define CP16(saddr, gptr) \
    asm volatile("cp.async.cg.shared.global [%0], [%1], 16;" \
                 :: "r"(saddr), "l"(gptr) : "memory")
#define CP_COMMIT() asm volatile("cp.async.commit_group;" ::: "memory")
#define CP_WAIT0()  asm volatile("cp.async.wait_group 0;" ::: "memory")
#define CP_WAIT1()  asm volatile("cp.async.wait_group 1;" ::: "memory")

#define LDSM4(r0, r1, r2, r3, addr)                                            \
    asm volatile("ldmatrix.sync.aligned.m8n8.x4.shared.b16 {%0,%1,%2,%3}, [%4];" \
                 : "=r"(r0), "=r"(r1), "=r"(r2), "=r"(r3) : "r"(addr))

#define MMA_OP(c, a, b)                                                        \
    asm volatile(                                                              \
        "mma.sync.aligned.m16n8k16.row.col.f32.bf16.bf16.f32 "                 \
        "{%0,%1,%2,%3}, {%4,%5,%6,%7}, {%8,%9}, {%0,%1,%2,%3};"                \
        : "+f"((c)[0]), "+f"((c)[1]), "+f"((c)[2]), "+f"((c)[3])               \
        : "r"((a)[0]), "r"((a)[1]), "r"((a)[2]), "r"((a)[3]),                  \
          "r"((b)[0]), "r"((b)[1]))

// smem tile geometry: 128 rows x 32 k, row stride 40 bf16 (80 B, LDSM-clean)
#define TROW 40
#define TELEM (128 * TROW)
#define STAGE_ELEM (4 * TELEM)
#define GEMM_SMEM (2 * STAGE_ELEM * 2)

// ===========================================================================
// bf16 hi/lo split GEMM + fused attention-scalar epilogue
// ===========================================================================
__global__ __launch_bounds__(256) void gemm_bf16_kernel(
    const __nv_bfloat16* __restrict__ Ahi, const __nv_bfloat16* __restrict__ Alo,
    const __nv_bfloat16* __restrict__ Bhi, const __nv_bfloat16* __restrict__ Blo,
    float* __restrict__ C, int M, int KTOT, int ldc,
    const float* __restrict__ attS0, const float* __restrict__ attS1,
    const float* __restrict__ attD0, const float* __restrict__ attD1,
    int hshift, float* __restrict__ asrc, float* __restrict__ adst)
{
    extern __shared__ __nv_bfloat16 sm[];
    const uint32_t sbase = smem_u32(sm);

    const int tid = threadIdx.x, warp = tid >> 5, lane = tid & 31;
    const int wm = warp & 1, wn = warp >> 1;
    const int row0 = blockIdx.y * 128;
    const int col0 = blockIdx.x * 128;
    const int nch = KTOT >> 5;

    float acc[4][4][4];
#pragma unroll
    for (int mt = 0; mt < 4; mt++)
#pragma unroll
        for (int nt = 0; nt < 4; nt++)
#pragma unroll
            for (int i = 0; i < 4; i++) acc[mt][nt][i] = 0.f;

    auto issue = [&](int stage, int kb) {
        const int so = stage * STAGE_ELEM;
#pragma unroll
        for (int it = 0; it < 2; it++) {
            int vec = tid + it * 256;
            int m = vec >> 2, ko = (vec & 3) * 8;
            uint32_t sd = sbase + (uint32_t)(so + m * TROW + ko) * 2;
            size_t ga = (size_t)(row0 + m) * KTOT + kb + ko;
            CP16(sd,             Ahi + ga);
            CP16(sd + TELEM * 2, Alo + ga);
            size_t gb = (size_t)(col0 + m) * KTOT + kb + ko;
            CP16(sd + TELEM * 4, Bhi + gb);
            CP16(sd + TELEM * 6, Blo + gb);
        }
        CP_COMMIT();
    };

    issue(0, 0);

    const int arow = wm * 64 + (lane & 15);
    const int acol = (lane >> 4) * 8;
    const int bmid = lane >> 3, brin = lane & 7;

    for (int c = 0; c < nch; c++) {
        if (c + 1 < nch) { issue((c + 1) & 1, (c + 1) * 32); CP_WAIT1(); }
        else             { CP_WAIT0(); }
        __syncthreads();

        const uint32_t aAh = sbase + (uint32_t)((c & 1) * STAGE_ELEM) * 2;
        const uint32_t aAl = aAh + TELEM * 2;
        const uint32_t aBh = aAh + TELEM * 4;
        const uint32_t aBl = aAh + TELEM * 6;

#pragma unroll
        for (int ks = 0; ks < 2; ks++) {
            const int k0 = ks * 16;
            uint32_t ah[4][4], al[4][4];
#pragma unroll
            for (int mt = 0; mt < 4; mt++) {
                uint32_t off = (uint32_t)((arow + mt * 16) * TROW + k0 + acol) * 2;
                LDSM4(ah[mt][0], ah[mt][1], ah[mt][2], ah[mt][3], aAh + off);
                LDSM4(al[mt][0], al[mt][1], al[mt][2], al[mt][3], aAl + off);
            }
            uint32_t bh[4][2], bl[4][2];
#pragma unroll
            for (int p = 0; p < 2; p++) {
                int bn = wn * 32 + p * 16 + (bmid >> 1) * 8 + brin;
                int bc = k0 + (bmid & 1) * 8;
                uint32_t off = (uint32_t)(bn * TROW + bc) * 2;
                uint32_t r0, r1, r2, r3;
                LDSM4(r0, r1, r2, r3, aBh + off);
                bh[p * 2][0] = r0; bh[p * 2][1] = r1;
                bh[p * 2 + 1][0] = r2; bh[p * 2 + 1][1] = r3;
                LDSM4(r0, r1, r2, r3, aBl + off);
                bl[p * 2][0] = r0; bl[p * 2][1] = r1;
                bl[p * 2 + 1][0] = r2; bl[p * 2 + 1][1] = r3;
            }
#pragma unroll
            for (int mt = 0; mt < 4; mt++)
#pragma unroll
                for (int nt = 0; nt < 4; nt++) {
                    MMA_OP(acc[mt][nt], ah[mt], bh[nt]);
                    MMA_OP(acc[mt][nt], ah[mt], bl[nt]);
                    MMA_OP(acc[mt][nt], al[mt], bh[nt]);
                }
        }
        __syncthreads();
    }

    const int qrow = lane >> 2, qcol = (lane & 3) * 2;

#pragma unroll
    for (int mt = 0; mt < 4; mt++) {
#pragma unroll
        for (int nt = 0; nt < 4; nt++) {
            int r = row0 + wm * 64 + mt * 16 + qrow;
            int cc = col0 + wn * 32 + nt * 8 + qcol;
            if (r < M)
                *(float2*)&C[(size_t)r * ldc + cc] =
                    make_float2(acc[mt][nt][0], acc[mt][nt][1]);
            if (r + 8 < M)
                *(float2*)&C[(size_t)(r + 8) * ldc + cc] =
                    make_float2(acc[mt][nt][2], acc[mt][nt][3]);
        }
    }

    // ---- fused attention scalars
    const int hmask = (1 << hshift) - 1;
    const int h = (col0 + wn * 32) >> hshift;
    const float* aS = h ? attS1 : attS0;
    const float* aD = h ? attD1 : attD0;
    float ws[4][2], wd[4][2];
#pragma unroll
    for (int nt = 0; nt < 4; nt++) {
        int ci = (col0 + wn * 32 + nt * 8 + qcol) & hmask;
        ws[nt][0] = aS[ci];     ws[nt][1] = aS[ci + 1];
        wd[nt][0] = aD[ci];     wd[nt][1] = aD[ci + 1];
    }
#pragma unroll
    for (int mt = 0; mt < 4; mt++) {
        float slo = 0.f, shi = 0.f, dlo = 0.f, dhi = 0.f;
#pragma unroll
        for (int nt = 0; nt < 4; nt++) {
            slo += acc[mt][nt][0] * ws[nt][0] + acc[mt][nt][1] * ws[nt][1];
            shi += acc[mt][nt][2] * ws[nt][0] + acc[mt][nt][3] * ws[nt][1];
            dlo += acc[mt][nt][0] * wd[nt][0] + acc[mt][nt][1] * wd[nt][1];
            dhi += acc[mt][nt][2] * wd[nt][0] + acc[mt][nt][3] * wd[nt][1];
        }
#pragma unroll
        for (int o = 1; o <= 2; o <<= 1) {
            slo += __shfl_xor_sync(~0u, slo, o);
            shi += __shfl_xor_sync(~0u, shi, o);
            dlo += __shfl_xor_sync(~0u, dlo, o);
            dhi += __shfl_xor_sync(~0u, dhi, o);
        }
        if ((lane & 3) == 0) {
            int r = row0 + wm * 64 + mt * 16 + qrow;
            if (r < M) {
                atomicAdd(&asrc[r * 2 + h], slo);
                atomicAdd(&adst[r * 2 + h], dlo);
            }
            if (r + 8 < M) {
                atomicAdd(&asrc[(r + 8) * 2 + h], shi);
                atomicAdd(&adst[(r + 8) * 2 + h], dhi);
            }
        }
    }
}

// ---------------------------------------------------------------------------
__global__ void zero_all_kernel(int* __restrict__ deg,
                                float* __restrict__ a1, float* __restrict__ d1,
                                float* __restrict__ a2, float* __restrict__ d2,
                                int N)
{
    int i = blockIdx.x * blockDim.x + threadIdx.x;
    if (i >= N) return;
    deg[i] = 0;
    float2 z = make_float2(0.f, 0.f);
    *(float2*)&a1[i * 2] = z;
    *(float2*)&d1[i * 2] = z;
    *(float2*)&a2[i * 2] = z;
    *(float2*)&d2[i * 2] = z;
}

__global__ void cvt_all_kernel(const float* __restrict__ x,
                               const float* __restrict__ W1,
                               const float* __restrict__ Wmu,
                               const float* __restrict__ Wls,
                               __nv_bfloat16* __restrict__ xhi,
                               __nv_bfloat16* __restrict__ xlo,
                               __nv_bfloat16* __restrict__ w1hi,
                               __nv_bfloat16* __restrict__ w1lo,
                               __nv_bfloat16* __restrict__ w2hi,
                               __nv_bfloat16* __restrict__ w2lo,
                               int nx)
{
    int i = blockIdx.x * blockDim.x + threadIdx.x;
    float v;
    __nv_bfloat16* hi;
    __nv_bfloat16* lo;
    int o;
    if (i < nx) {
        v = x[i]; hi = xhi; lo = xlo; o = i;
    } else if (i < nx + 256 * 128) {
        o = i - nx;
        int n = o >> 7, k = o & 127;
        v = W1[k * 256 + n]; hi = w1hi; lo = w1lo;
    } else if (i < nx + 256 * 128 + 128 * 256) {
        o = i - nx - 256 * 128;
        int n = o >> 8, k = o & 255;
        v = (n < 64) ? Wmu[k * 64 + n] : Wls[k * 64 + n - 64];
        hi = w2hi; lo = w2lo;
    } else return;
    __nv_bfloat16 h = __float2bfloat16(v);
    hi[o] = h;
    lo[o] = __float2bfloat16(v - __bfloat162float(h));
}

// ---------------------------------------------------------------------------
// CSR build
// ---------------------------------------------------------------------------
__global__ void hist_kernel(const int* __restrict__ ei, int nE, int nTot,
                            int* __restrict__ deg)
{
    int e = blockIdx.x * blockDim.x + threadIdx.x;
    if (e >= nTot) return;
    int d = (e < nE) ? ei[nE + e] : e - nE;
    atomicAdd(&deg[d], 1);
}

__global__ __launch_bounds__(1024) void scan_kernel(
    const int* __restrict__ deg, int* __restrict__ off,
    int* __restrict__ cur, int N)
{
    __shared__ int ssum[1024];
    int tid = threadIdx.x;
    int chunk = (N + 1023) / 1024;
    int start = tid * chunk;
    int end = min(start + chunk, N);
    int s = 0;
    for (int i = start; i < end; i++) s += deg[i];
    ssum[tid] = s;
    __syncthreads();
    for (int o = 1; o < 1024; o <<= 1) {
        int v = 0;
        if (tid >= o) v = ssum[tid - o];
        __syncthreads();
        if (tid >= o) ssum[tid] += v;
        __syncthreads();
    }
    int base = (tid > 0) ? ssum[tid - 1] : 0;
    for (int i = start; i < end; i++) {
        off[i] = base;
        cur[i] = base;
        base += deg[i];
    }
    if (tid == 1023) off[N] = ssum[1023];
}

__global__ void scatter_kernel(const int* __restrict__ ei, int nE, int nTot,
                               int* __restrict__ cur, int* __restrict__ csr)
{
    int e = blockIdx.x * blockDim.x + threadIdx.x;
    if (e >= nTot) return;
    int s, d;
    if (e < nE) { s = ei[e]; d = ei[nE + e]; }
    else        { s = e - nE; d = s; }
    int pos = atomicAdd(&cur[d], 1);
    csr[pos] = s;
}

// ---------------------------------------------------------------------------
__device__ __forceinline__ float lrelu(float v) { return v > 0.f ? v : NEG_SLOPE * v; }

// ---------------------------------------------------------------------------
// layer-1 agg: warp per node, both heads; online softmax; 2-edge x 2-head gather
// ---------------------------------------------------------------------------
__global__ void agg1_kernel(const int* __restrict__ off, const int* __restrict__ csr,
                            const float* __restrict__ asrc, const float* __restrict__ adst,
                            const float* __restrict__ feat, const float* __restrict__ bias,
                            __nv_bfloat16* __restrict__ ohi,
                            __nv_bfloat16* __restrict__ olo, int Nn)
{
    int warpi = (blockIdx.x * blockDim.x + threadIdx.x) >> 5;
    int lane = threadIdx.x & 31;
    if (warpi >= Nn) return;
    int n = warpi;
    int o0 = off[n], o1 = off[n + 1];
    float2 adv = *(const float2*)&adst[n * 2];

    float m0 = -1e30f, d0 = 0.f, m1 = -1e30f, d1 = 0.f;
    for (int j = o0 + lane; j < o1; j += 32) {
        float2 a = *(const float2*)&asrc[csr[j] * 2];
        float e0 = lrelu(a.x + adv.x);
        float e1 = lrelu(a.y + adv.y);
        float nm0 = fmaxf(m0, e0);
        d0 = d0 * __expf(m0 - nm0) + __expf(e0 - nm0);
        m0 = nm0;
        float nm1 = fmaxf(m1, e1);
        d1 = d1 * __expf(m1 - nm1) + __expf(e1 - nm1);
        m1 = nm1;
    }
#pragma unroll
    for (int o = 16; o; o >>= 1) {
        float mo = __shfl_xor_sync(~0u, m0, o), dd = __shfl_xor_sync(~0u, d0, o);
        float nm = fmaxf(m0, mo);
        d0 = d0 * __expf(m0 - nm) + dd * __expf(mo - nm);
        m0 = nm;
        mo = __shfl_xor_sync(~0u, m1, o); dd = __shfl_xor_sync(~0u, d1, o);
        nm = fmaxf(m1, mo);
        d1 = d1 * __expf(m1 - nm) + dd * __expf(mo - nm);
        m1 = nm;
    }
    float inv0 = 1.f / (d0 + 1e-16f);
    float inv1 = 1.f / (d1 + 1e-16f);

    const float* f0 = feat + lane * 4;
    const float* f1 = feat + 128 + lane * 4;
    float4 acc0 = make_float4(0.f, 0.f, 0.f, 0.f);
    float4 acc1 = make_float4(0.f, 0.f, 0.f, 0.f);
    int j = o0;
    for (; j + 1 < o1; j += 2) {
        int s0 = csr[j], s1 = csr[j + 1];
        float2 a0 = *(const float2*)&asrc[s0 * 2];
        float2 a1 = *(const float2*)&asrc[s1 * 2];
        float w00 = __expf(lrelu(a0.x + adv.x) - m0) * inv0;
        float w01 = __expf(lrelu(a0.y + adv.y) - m1) * inv1;
        float w10 = __expf(lrelu(a1.x + adv.x) - m0) * inv0;
        float w11 = __expf(lrelu(a1.y + adv.y) - m1) * inv1;
        float4 p00 = *(const float4*)(f0 + (size_t)s0 * 256);
        float4 p01 = *(const float4*)(f1 + (size_t)s0 * 256);
        float4 p10 = *(const float4*)(f0 + (size_t)s1 * 256);
        float4 p11 = *(const float4*)(f1 + (size_t)s1 * 256);
        acc0.x += w00 * p00.x + w10 * p10.x;
        acc0.y += w00 * p00.y + w10 * p10.y;
        acc0.z += w00 * p00.z + w10 * p10.z;
        acc0.w += w00 * p00.w + w10 * p10.w;
        acc1.x += w01 * p01.x + w11 * p11.x;
        acc1.y += w01 * p01.y + w11 * p11.y;
        acc1.z += w01 * p01.z + w11 * p11.z;
        acc1.w += w01 * p01.w + w11 * p11.w;
    }
    for (; j < o1; j++) {
        int s = csr[j];
        float2 a = *(const float2*)&asrc[s * 2];
        float w0 = __expf(lrelu(a.x + adv.x) - m0) * inv0;
        float w1 = __expf(lrelu(a.y + adv.y) - m1) * inv1;
        float4 p0 = *(const float4*)(f0 + (size_t)s * 256);
        float4 p1 = *(const float4*)(f1 + (size_t)s * 256);
        acc0.x += w0 * p0.x; acc0.y += w0 * p0.y;
        acc0.z += w0 * p0.z; acc0.w += w0 * p0.w;
        acc1.x += w1 * p1.x; acc1.y += w1 * p1.y;
        acc1.z += w1 * p1.z; acc1.w += w1 * p1.w;
    }

    float4 b0 = *(const float4*)(bias + lane * 4);
    float4 b1 = *(const float4*)(bias + 128 + lane * 4);
    float vv0[4] = {acc0.x + b0.x, acc0.y + b0.y, acc0.z + b0.z, acc0.w + b0.w};
    float vv1[4] = {acc1.x + b1.x, acc1.y + b1.y, acc1.z + b1.z, acc1.w + b1.w};
    ushort4 hv0, lv0, hv1, lv1;
    unsigned short *hp0 = &hv0.x, *lp0 = &lv0.x, *hp1 = &hv1.x, *lp1 = &lv1.x;
#pragma unroll
    for (int q = 0; q < 4; q++) {
        float e0 = vv0[q] > 0.f ? vv0[q] : expm1f(vv0[q]);
        __nv_bfloat16 hb = __float2bfloat16(e0);
        hp0[q] = __bfloat16_as_ushort(hb);
        lp0[q] = __bfloat16_as_ushort(__float2bfloat16(e0 - __bfloat162float(hb)));
        float e1 = vv1[q] > 0.f ? vv1[q] : expm1f(vv1[q]);
        hb = __float2bfloat16(e1);
        hp1[q] = __bfloat16_as_ushort(hb);
        lp1[q] = __bfloat16_as_ushort(__float2bfloat16(e1 - __bfloat162float(hb)));
    }
    size_t idx = (size_t)n * 256 + lane * 4;
    *(ushort4*)&ohi[idx] = hv0;
    *(ushort4*)&olo[idx] = lv0;
    *(ushort4*)&ohi[idx + 128] = hv1;
    *(ushort4*)&olo[idx + 128] = lv1;
}

// ---------------------------------------------------------------------------
// layer-2 agg: warp per node, heads on half-warps, online softmax stats
// ---------------------------------------------------------------------------
__global__ void agg2_kernel(const int* __restrict__ off, const int* __restrict__ csr,
                            const float* __restrict__ asrc, const float* __restrict__ adst,
                            const float* __restrict__ feat,
                            const float* __restrict__ bmu, const float* __restrict__ bls,
                            float* __restrict__ out, long headStride, int Nn)
{
    int warpi = (blockIdx.x * blockDim.x + threadIdx.x) >> 5;
    int lane = threadIdx.x & 31;
    if (warpi >= Nn) return;
    int n = warpi;
    int h = lane >> 4, l = lane & 15;
    int o0 = off[n], o1 = off[n + 1];
    float ad = adst[n * 2 + h];

    float m = -1e30f, den = 0.f;
    for (int j = o0 + l; j < o1; j += 16) {
        float e = lrelu(asrc[csr[j] * 2 + h] + ad);
        float nm = fmaxf(m, e);
        den = den * __expf(m - nm) + __expf(e - nm);
        m = nm;
    }
#pragma unroll
    for (int o = 8; o; o >>= 1) {
        float mo = __shfl_xor_sync(~0u, m, o), dd = __shfl_xor_sync(~0u, den, o);
        float nm = fmaxf(m, mo);
        den = den * __expf(m - nm) + dd * __expf(mo - nm);
        m = nm;
    }
    float inv = 1.f / (den + 1e-16f);

    float4 acc = make_float4(0.f, 0.f, 0.f, 0.f);
    const float* fb = feat + h * 64 + l * 4;
    int j = o0;
    for (; j + 3 < o1; j += 4) {
        int s0 = csr[j], s1 = csr[j + 1], s2 = csr[j + 2], s3 = csr[j + 3];
        float a0 = __expf(lrelu(asrc[s0 * 2 + h] + ad) - m) * inv;
        float a1 = __expf(lrelu(asrc[s1 * 2 + h] + ad) - m) * inv;
        float a2 = __expf(lrelu(asrc[s2 * 2 + h] + ad) - m) * inv;
        float a3 = __expf(lrelu(asrc[s3 * 2 + h] + ad) - m) * inv;
        float4 p0 = *(const float4*)(fb + (size_t)s0 * 128);
        float4 p1 = *(const float4*)(fb + (size_t)s1 * 128);
        float4 p2 = *(const float4*)(fb + (size_t)s2 * 128);
        float4 p3 = *(const float4*)(fb + (size_t)s3 * 128);
        acc.x += a0 * p0.x + a1 * p1.x + a2 * p2.x + a3 * p3.x;
        acc.y += a0 * p0.y + a1 * p1.y + a2 * p2.y + a3 * p3.y;
        acc.z += a0 * p0.z + a1 * p1.z + a2 * p2.z + a3 * p3.z;
        acc.w += a0 * p0.w + a1 * p1.w + a2 * p2.w + a3 * p3.w;
    }
    for (; j < o1; j++) {
        int s = csr[j];
        float a = __expf(lrelu(asrc[s * 2 + h] + ad) - m) * inv;
        float4 p = *(const float4*)(fb + (size_t)s * 128);
        acc.x += a * p.x; acc.y += a * p.y; acc.z += a * p.z; acc.w += a * p.w;
    }

    float4 b4 = *(const float4*)((h ? bls : bmu) + l * 4);
    acc.x += b4.x; acc.y += b4.y; acc.z += b4.z; acc.w += b4.w;
    *(float4*)&out[(size_t)h * headStride + (size_t)n * 64 + l * 4] = acc;
}

// ---------------------------------------------------------------------------
static inline int cdiv(long a, int b) { return (int)((a + b - 1) / b); }

extern "C" void kernel_launch(void* const* d_in, const int* in_sizes, int n_in,
                              void* d_out, int out_size)
{
    const float* x          = (const float*)d_in[0];
    const int*   edge_index = (const int*)d_in[1];
    const float* W1         = (const float*)d_in[2];
    const float* att_src1   = (const float*)d_in[3];
    const float* att_dst1   = (const float*)d_in[4];
    const float* b1         = (const float*)d_in[5];
    const float* W_mu       = (const float*)d_in[6];
    const float* att_src_mu = (const float*)d_in[7];
    const float* att_dst_mu = (const float*)d_in[8];
    const float* b_mu       = (const float*)d_in[9];
    const float* W_ls       = (const float*)d_in[10];
    const float* att_src_ls = (const float*)d_in[11];
    const float* att_dst_ls = (const float*)d_in[12];
    const float* b_ls       = (const float*)d_in[13];
    float* out = (float*)d_out;

    const int N  = in_sizes[0] / 128;
    const int nE = in_sizes[1] / 2;
    const int nTot = nE + N;

    float *p_h1, *p_h2, *p_as1, *p_ad1, *p_as2, *p_ad2;
    int *p_deg, *p_off, *p_cur, *p_csr;
    __nv_bfloat16 *p_xhi, *p_xlo, *p_a2hi, *p_a2lo, *p_w1hi, *p_w1lo, *p_w2hi, *p_w2lo;
    cudaGetSymbolAddress((void**)&p_h1,   g_h1);
    cudaGetSymbolAddress((void**)&p_h2,   g_h2);
    cudaGetSymbolAddress((void**)&p_as1,  g_asrc1);
    cudaGetSymbolAddress((void**)&p_ad1,  g_adst1);
    cudaGetSymbolAddress((void**)&p_as2,  g_asrc2);
    cudaGetSymbolAddress((void**)&p_ad2,  g_adst2);
    cudaGetSymbolAddress((void**)&p_deg,  g_deg);
    cudaGetSymbolAddress((void**)&p_off,  g_off);
    cudaGetSymbolAddress((void**)&p_cur,  g_cur);
    cudaGetSymbolAddress((void**)&p_csr,  g_csr);
    cudaGetSymbolAddress((void**)&p_xhi,  g_xhi);
    cudaGetSymbolAddress((void**)&p_xlo,  g_xlo);
    cudaGetSymbolAddress((void**)&p_a2hi, g_a2hi);
    cudaGetSymbolAddress((void**)&p_a2lo, g_a2lo);
    cudaGetSymbolAddress((void**)&p_w1hi, g_w1hi);
    cudaGetSymbolAddress((void**)&p_w1lo, g_w1lo);
    cudaGetSymbolAddress((void**)&p_w2hi, g_w2hi);
    cudaGetSymbolAddress((void**)&p_w2lo, g_w2lo);

    cudaFuncSetAttribute(gemm_bf16_kernel,
                         cudaFuncAttributeMaxDynamicSharedMemorySize, GEMM_SMEM);

    const int T = 256;

    // 1) zero deg + att-scalar buffers
    zero_all_kernel<<<cdiv(N, T), T>>>(p_deg, p_as1, p_ad1, p_as2, p_ad2, N);
    // 2-4) CSR build
    hist_kernel<<<cdiv(nTot, T), T>>>(edge_index, nE, nTot, p_deg);
    scan_kernel<<<1, 1024>>>(p_deg, p_off, p_cur, N);
    scatter_kernel<<<cdiv(nTot, T), T>>>(edge_index, nE, nTot, p_cur, p_csr);
    // 5) operand conversion (x, W1, W2 merged)
    {
        long total = (long)N * 128 + 256 * 128 + 128 * 256;
        cvt_all_kernel<<<cdiv(total, T), T>>>(x, W1, W_mu, W_ls,
            p_xhi, p_xlo, p_w1hi, p_w1lo, p_w2hi, p_w2lo, N * 128);
    }
    // 6) layer-1 GEMM + fused att scalars
    {
        dim3 grid(2, cdiv(N, 128));
        gemm_bf16_kernel<<<grid, 256, GEMM_SMEM>>>(
            p_xhi, p_xlo, p_w1hi, p_w1lo, p_h1, N, 128, 256,
            att_src1, att_src1 + 128, att_dst1, att_dst1 + 128, 7, p_as1, p_ad1);
    }
    // 7) layer-1 aggregation (warp per node, both heads)
    agg1_kernel<<<cdiv((long)N * 32, T), T>>>(
        p_off, p_csr, p_as1, p_ad1, p_h1, b1, p_a2hi, p_a2lo, N);
    // 8) layer-2 GEMM + fused att scalars
    {
        dim3 grid(1, cdiv(N, 128));
        gemm_bf16_kernel<<<grid, 256, GEMM_SMEM>>>(
            p_a2hi, p_a2lo, p_w2hi, p_w2lo, p_h2, N, 256, 128,
            att_src_mu, att_src_ls, att_dst_mu, att_dst_ls, 6, p_as2, p_ad2);
    }
    // 9) layer-2 aggregation -> output
    agg2_kernel<<<cdiv((long)N * 32, T), T>>>(
        p_off, p_csr, p_as2, p_ad2, p_h2, b_mu, b_ls, out, (long)N * 64, N);
}

// round 14
// speedup vs baseline: 1.5110x; 1.0015x over previous
#include <cuda_runtime.h>
#include <cuda_bf16.h>
#include <cstdint>
#include <stdint.h>
#include <math.h>

#define MAX_N 50000
#define MAX_E 400000
#define MAX_ETOT (MAX_N + MAX_E)
#define NEG_SLOPE 0.2f
#define NPAD (MAX_N + 128)

// ---------------- scratch (device globals, allocation-free) ----------------
__device__ float g_h1[MAX_N * 256];    // conv1 features  [N,2,128]
__device__ float g_h2[MAX_N * 128];    // layer2 feats    [N,{mu,ls},64]
__device__ float g_asrc1[MAX_N * 2];
__device__ float g_adst1[MAX_N * 2];
__device__ float g_asrc2[MAX_N * 2];
__device__ float g_adst2[MAX_N * 2];
__device__ int   g_deg[MAX_N];
__device__ int   g_off[MAX_N + 1];
__device__ int   g_cur[MAX_N];
__device__ int   g_csr[MAX_ETOT];      // src node per CSR slot (sorted by dst)

// bf16 hi/lo operand arrays (zero-initialized; padding rows stay 0)
__device__ __nv_bfloat16 g_xhi[NPAD * 128],  g_xlo[NPAD * 128];   // layer1 A
__device__ __nv_bfloat16 g_a2hi[NPAD * 256], g_a2lo[NPAD * 256];  // layer2 A (ELU out)
__device__ __nv_bfloat16 g_w1hi[256 * 128],  g_w1lo[256 * 128];   // layer1 B  [n][k]
__device__ __nv_bfloat16 g_w2hi[128 * 256],  g_w2lo[128 * 256];   // layer2 B  [n][k]

// ======================= PTX helpers ======================================
__device__ __forceinline__ uint32_t smem_u32(const void* p) {
    uint32_t a;
    asm("{ .reg .u64 t; cvta.to.shared.u64 t, %1; cvt.u32.u64 %0, t; }"
        : "=r"(a) : "l"(p));
    return a;
}

#define CP16(saddr, gptr) \
    asm volatile("cp.async.cg.shared.global [%0], [%1], 16;" \
                 :: "r"(saddr), "l"(gptr) : "memory")
#define CP_COMMIT() asm volatile("cp.async.commit_group;" ::: "memory")
#define CP_WAIT0()  asm volatile("cp.async.wait_group 0;" ::: "memory")
#define CP_WAIT1()  asm volatile("cp.async.wait_group 1;" ::: "memory")

#define LDSM4(r0, r1, r2, r3, addr)                                            \
    asm volatile("ldmatrix.sync.aligned.m8n8.x4.shared.b16 {%0,%1,%2,%3}, [%4];" \
                 : "=r"(r0), "=r"(r1), "=r"(r2), "=r"(r3) : "r"(addr))

#define MMA_OP(c, a, b)                                                        \
    asm volatile(                                                              \
        "mma.sync.aligned.m16n8k16.row.col.f32.bf16.bf16.f32 "                 \
        "{%0,%1,%2,%3}, {%4,%5,%6,%7}, {%8,%9}, {%0,%1,%2,%3};"                \
        : "+f"((c)[0]), "+f"((c)[1]), "+f"((c)[2]), "+f"((c)[3])               \
        : "r"((a)[0]), "r"((a)[1]), "r"((a)[2]), "r"((a)[3]),                  \
          "r"((b)[0]), "r"((b)[1]))

// smem tile geometry: 128 rows x 32 k, row stride 40 bf16 (80 B, LDSM-clean)
#define TROW 40
#define TELEM (128 * TROW)
#define STAGE_ELEM (4 * TELEM)
#define GEMM_SMEM (2 * STAGE_ELEM * 2)

// ===========================================================================
// bf16 hi/lo split GEMM + fused attention-scalar epilogue
// ===========================================================================
__global__ __launch_bounds__(256) void gemm_bf16_kernel(
    const __nv_bfloat16* __restrict__ Ahi, const __nv_bfloat16* __restrict__ Alo,
    const __nv_bfloat16* __restrict__ Bhi, const __nv_bfloat16* __restrict__ Blo,
    float* __restrict__ C, int M, int KTOT, int ldc,
    const float* __restrict__ attS0, const float* __restrict__ attS1,
    const float* __restrict__ attD0, const float* __restrict__ attD1,
    int hshift, float* __restrict__ asrc, float* __restrict__ adst)
{
    extern __shared__ __nv_bfloat16 sm[];
    const uint32_t sbase = smem_u32(sm);

    const int tid = threadIdx.x, warp = tid >> 5, lane = tid & 31;
    const int wm = warp & 1, wn = warp >> 1;
    const int row0 = blockIdx.y * 128;
    const int col0 = blockIdx.x * 128;
    const int nch = KTOT >> 5;

    float acc[4][4][4];
#pragma unroll
    for (int mt = 0; mt < 4; mt++)
#pragma unroll
        for (int nt = 0; nt < 4; nt++)
#pragma unroll
            for (int i = 0; i < 4; i++) acc[mt][nt][i] = 0.f;

    auto issue = [&](int stage, int kb) {
        const int so = stage * STAGE_ELEM;
#pragma unroll
        for (int it = 0; it < 2; it++) {
            int vec = tid + it * 256;
            int m = vec >> 2, ko = (vec & 3) * 8;
            uint32_t sd = sbase + (uint32_t)(so + m * TROW + ko) * 2;
            size_t ga = (size_t)(row0 + m) * KTOT + kb + ko;
            CP16(sd,             Ahi + ga);
            CP16(sd + TELEM * 2, Alo + ga);
            size_t gb = (size_t)(col0 + m) * KTOT + kb + ko;
            CP16(sd + TELEM * 4, Bhi + gb);
            CP16(sd + TELEM * 6, Blo + gb);
        }
        CP_COMMIT();
    };

    issue(0, 0);

    const int arow = wm * 64 + (lane & 15);
    const int acol = (lane >> 4) * 8;
    const int bmid = lane >> 3, brin = lane & 7;

    for (int c = 0; c < nch; c++) {
        if (c + 1 < nch) { issue((c + 1) & 1, (c + 1) * 32); CP_WAIT1(); }
        else             { CP_WAIT0(); }
        __syncthreads();

        const uint32_t aAh = sbase + (uint32_t)((c & 1) * STAGE_ELEM) * 2;
        const uint32_t aAl = aAh + TELEM * 2;
        const uint32_t aBh = aAh + TELEM * 4;
        const uint32_t aBl = aAh + TELEM * 6;

#pragma unroll
        for (int ks = 0; ks < 2; ks++) {
            const int k0 = ks * 16;
            uint32_t ah[4][4], al[4][4];
#pragma unroll
            for (int mt = 0; mt < 4; mt++) {
                uint32_t off = (uint32_t)((arow + mt * 16) * TROW + k0 + acol) * 2;
                LDSM4(ah[mt][0], ah[mt][1], ah[mt][2], ah[mt][3], aAh + off);
                LDSM4(al[mt][0], al[mt][1], al[mt][2], al[mt][3], aAl + off);
            }
            uint32_t bh[4][2], bl[4][2];
#pragma unroll
            for (int p = 0; p < 2; p++) {
                int bn = wn * 32 + p * 16 + (bmid >> 1) * 8 + brin;
                int bc = k0 + (bmid & 1) * 8;
                uint32_t off = (uint32_t)(bn * TROW + bc) * 2;
                uint32_t r0, r1, r2, r3;
                LDSM4(r0, r1, r2, r3, aBh + off);
                bh[p * 2][0] = r0; bh[p * 2][1] = r1;
                bh[p * 2 + 1][0] = r2; bh[p * 2 + 1][1] = r3;
                LDSM4(r0, r1, r2, r3, aBl + off);
                bl[p * 2][0] = r0; bl[p * 2][1] = r1;
                bl[p * 2 + 1][0] = r2; bl[p * 2 + 1][1] = r3;
            }
#pragma unroll
            for (int mt = 0; mt < 4; mt++)
#pragma unroll
                for (int nt = 0; nt < 4; nt++) {
                    MMA_OP(acc[mt][nt], ah[mt], bh[nt]);
                    MMA_OP(acc[mt][nt], ah[mt], bl[nt]);
                    MMA_OP(acc[mt][nt], al[mt], bh[nt]);
                }
        }
        __syncthreads();
    }

    const int qrow = lane >> 2, qcol = (lane & 3) * 2;

#pragma unroll
    for (int mt = 0; mt < 4; mt++) {
#pragma unroll
        for (int nt = 0; nt < 4; nt++) {
            int r = row0 + wm * 64 + mt * 16 + qrow;
            int cc = col0 + wn * 32 + nt * 8 + qcol;
            if (r < M)
                *(float2*)&C[(size_t)r * ldc + cc] =
                    make_float2(acc[mt][nt][0], acc[mt][nt][1]);
            if (r + 8 < M)
                *(float2*)&C[(size_t)(r + 8) * ldc + cc] =
                    make_float2(acc[mt][nt][2], acc[mt][nt][3]);
        }
    }

    // ---- fused attention scalars
    const int hmask = (1 << hshift) - 1;
    const int h = (col0 + wn * 32) >> hshift;
    const float* aS = h ? attS1 : attS0;
    const float* aD = h ? attD1 : attD0;
    float ws[4][2], wd[4][2];
#pragma unroll
    for (int nt = 0; nt < 4; nt++) {
        int ci = (col0 + wn * 32 + nt * 8 + qcol) & hmask;
        ws[nt][0] = aS[ci];     ws[nt][1] = aS[ci + 1];
        wd[nt][0] = aD[ci];     wd[nt][1] = aD[ci + 1];
    }
#pragma unroll
    for (int mt = 0; mt < 4; mt++) {
        float slo = 0.f, shi = 0.f, dlo = 0.f, dhi = 0.f;
#pragma unroll
        for (int nt = 0; nt < 4; nt++) {
            slo += acc[mt][nt][0] * ws[nt][0] + acc[mt][nt][1] * ws[nt][1];
            shi += acc[mt][nt][2] * ws[nt][0] + acc[mt][nt][3] * ws[nt][1];
            dlo += acc[mt][nt][0] * wd[nt][0] + acc[mt][nt][1] * wd[nt][1];
            dhi += acc[mt][nt][2] * wd[nt][0] + acc[mt][nt][3] * wd[nt][1];
        }
#pragma unroll
        for (int o = 1; o <= 2; o <<= 1) {
            slo += __shfl_xor_sync(~0u, slo, o);
            shi += __shfl_xor_sync(~0u, shi, o);
            dlo += __shfl_xor_sync(~0u, dlo, o);
            dhi += __shfl_xor_sync(~0u, dhi, o);
        }
        if ((lane & 3) == 0) {
            int r = row0 + wm * 64 + mt * 16 + qrow;
            if (r < M) {
                atomicAdd(&asrc[r * 2 + h], slo);
                atomicAdd(&adst[r * 2 + h], dlo);
            }
            if (r + 8 < M) {
                atomicAdd(&asrc[(r + 8) * 2 + h], shi);
                atomicAdd(&adst[(r + 8) * 2 + h], dhi);
            }
        }
    }
}

// ---------------------------------------------------------------------------
__global__ void zero_all_kernel(int* __restrict__ deg,
                                float* __restrict__ a1, float* __restrict__ d1,
                                float* __restrict__ a2, float* __restrict__ d2,
                                int N)
{
    int i = blockIdx.x * blockDim.x + threadIdx.x;
    if (i >= N) return;
    deg[i] = 0;
    float2 z = make_float2(0.f, 0.f);
    *(float2*)&a1[i * 2] = z;
    *(float2*)&d1[i * 2] = z;
    *(float2*)&a2[i * 2] = z;
    *(float2*)&d2[i * 2] = z;
}

__global__ void cvt_all_kernel(const float* __restrict__ x,
                               const float* __restrict__ W1,
                               const float* __restrict__ Wmu,
                               const float* __restrict__ Wls,
                               __nv_bfloat16* __restrict__ xhi,
                               __nv_bfloat16* __restrict__ xlo,
                               __nv_bfloat16* __restrict__ w1hi,
                               __nv_bfloat16* __restrict__ w1lo,
                               __nv_bfloat16* __restrict__ w2hi,
                               __nv_bfloat16* __restrict__ w2lo,
                               int nx)
{
    int i = blockIdx.x * blockDim.x + threadIdx.x;
    float v;
    __nv_bfloat16* hi;
    __nv_bfloat16* lo;
    int o;
    if (i < nx) {
        v = x[i]; hi = xhi; lo = xlo; o = i;
    } else if (i < nx + 256 * 128) {
        o = i - nx;
        int n = o >> 7, k = o & 127;
        v = W1[k * 256 + n]; hi = w1hi; lo = w1lo;
    } else if (i < nx + 256 * 128 + 128 * 256) {
        o = i - nx - 256 * 128;
        int n = o >> 8, k = o & 255;
        v = (n < 64) ? Wmu[k * 64 + n] : Wls[k * 64 + n - 64];
        hi = w2hi; lo = w2lo;
    } else return;
    __nv_bfloat16 h = __float2bfloat16(v);
    hi[o] = h;
    lo[o] = __float2bfloat16(v - __bfloat162float(h));
}

// ---------------------------------------------------------------------------
// CSR build
// ---------------------------------------------------------------------------
__global__ void hist_kernel(const int* __restrict__ ei, int nE, int nTot,
                            int* __restrict__ deg)
{
    int e = blockIdx.x * blockDim.x + threadIdx.x;
    if (e >= nTot) return;
    int d = (e < nE) ? ei[nE + e] : e - nE;
    atomicAdd(&deg[d], 1);
}

__global__ __launch_bounds__(1024) void scan_kernel(
    const int* __restrict__ deg, int* __restrict__ off,
    int* __restrict__ cur, int N)
{
    __shared__ int ssum[1024];
    int tid = threadIdx.x;
    int chunk = (N + 1023) / 1024;
    int start = tid * chunk;
    int end = min(start + chunk, N);
    int s = 0;
    for (int i = start; i < end; i++) s += deg[i];
    ssum[tid] = s;
    __syncthreads();
    for (int o = 1; o < 1024; o <<= 1) {
        int v = 0;
        if (tid >= o) v = ssum[tid - o];
        __syncthreads();
        if (tid >= o) ssum[tid] += v;
        __syncthreads();
    }
    int base = (tid > 0) ? ssum[tid - 1] : 0;
    for (int i = start; i < end; i++) {
        off[i] = base;
        cur[i] = base;
        base += deg[i];
    }
    if (tid == 1023) off[N] = ssum[1023];
}

__global__ void scatter_kernel(const int* __restrict__ ei, int nE, int nTot,
                               int* __restrict__ cur, int* __restrict__ csr)
{
    int e = blockIdx.x * blockDim.x + threadIdx.x;
    if (e >= nTot) return;
    int s, d;
    if (e < nE) { s = ei[e]; d = ei[nE + e]; }
    else        { s = e - nE; d = s; }
    int pos = atomicAdd(&cur[d], 1);
    csr[pos] = s;
}

// ---------------------------------------------------------------------------
__device__ __forceinline__ float lrelu(float v) { return v > 0.f ? v : NEG_SLOPE * v; }

// ---------------------------------------------------------------------------
// layer-1 agg: warp per node, both heads; online softmax; 2-edge x 2-head gather
// ---------------------------------------------------------------------------
__global__ void agg1_kernel(const int* __restrict__ off, const int* __restrict__ csr,
                            const float* __restrict__ asrc, const float* __restrict__ adst,
                            const float* __restrict__ feat, const float* __restrict__ bias,
                            __nv_bfloat16* __restrict__ ohi,
                            __nv_bfloat16* __restrict__ olo, int Nn)
{
    int warpi = (blockIdx.x * blockDim.x + threadIdx.x) >> 5;
    int lane = threadIdx.x & 31;
    if (warpi >= Nn) return;
    int n = warpi;
    int o0 = off[n], o1 = off[n + 1];
    float2 adv = *(const float2*)&adst[n * 2];

    float m0 = -1e30f, d0 = 0.f, m1 = -1e30f, d1 = 0.f;
    for (int j = o0 + lane; j < o1; j += 32) {
        float2 a = *(const float2*)&asrc[csr[j] * 2];
        float e0 = lrelu(a.x + adv.x);
        float e1 = lrelu(a.y + adv.y);
        float nm0 = fmaxf(m0, e0);
        d0 = d0 * __expf(m0 - nm0) + __expf(e0 - nm0);
        m0 = nm0;
        float nm1 = fmaxf(m1, e1);
        d1 = d1 * __expf(m1 - nm1) + __expf(e1 - nm1);
        m1 = nm1;
    }
#pragma unroll
    for (int o = 16; o; o >>= 1) {
        float mo = __shfl_xor_sync(~0u, m0, o), dd = __shfl_xor_sync(~0u, d0, o);
        float nm = fmaxf(m0, mo);
        d0 = d0 * __expf(m0 - nm) + dd * __expf(mo - nm);
        m0 = nm;
        mo = __shfl_xor_sync(~0u, m1, o); dd = __shfl_xor_sync(~0u, d1, o);
        nm = fmaxf(m1, mo);
        d1 = d1 * __expf(m1 - nm) + dd * __expf(mo - nm);
        m1 = nm;
    }
    float inv0 = 1.f / (d0 + 1e-16f);
    float inv1 = 1.f / (d1 + 1e-16f);

    const float* f0 = feat + lane * 4;
    const float* f1 = feat + 128 + lane * 4;
    float4 acc0 = make_float4(0.f, 0.f, 0.f, 0.f);
    float4 acc1 = make_float4(0.f, 0.f, 0.f, 0.f);
    int j = o0;
    for (; j + 1 < o1; j += 2) {
        int s0 = csr[j], s1 = csr[j + 1];
        float2 a0 = *(const float2*)&asrc[s0 * 2];
        float2 a1 = *(const float2*)&asrc[s1 * 2];
        float w00 = __expf(lrelu(a0.x + adv.x) - m0) * inv0;
        float w01 = __expf(lrelu(a0.y + adv.y) - m1) * inv1;
        float w10 = __expf(lrelu(a1.x + adv.x) - m0) * inv0;
        float w11 = __expf(lrelu(a1.y + adv.y) - m1) * inv1;
        float4 p00 = *(const float4*)(f0 + (size_t)s0 * 256);
        float4 p01 = *(const float4*)(f1 + (size_t)s0 * 256);
        float4 p10 = *(const float4*)(f0 + (size_t)s1 * 256);
        float4 p11 = *(const float4*)(f1 + (size_t)s1 * 256);
        acc0.x += w00 * p00.x + w10 * p10.x;
        acc0.y += w00 * p00.y + w10 * p10.y;
        acc0.z += w00 * p00.z + w10 * p10.z;
        acc0.w += w00 * p00.w + w10 * p10.w;
        acc1.x += w01 * p01.x + w11 * p11.x;
        acc1.y += w01 * p01.y + w11 * p11.y;
        acc1.z += w01 * p01.z + w11 * p11.z;
        acc1.w += w01 * p01.w + w11 * p11.w;
    }
    for (; j < o1; j++) {
        int s = csr[j];
        float2 a = *(const float2*)&asrc[s * 2];
        float w0 = __expf(lrelu(a.x + adv.x) - m0) * inv0;
        float w1 = __expf(lrelu(a.y + adv.y) - m1) * inv1;
        float4 p0 = *(const float4*)(f0 + (size_t)s * 256);
        float4 p1 = *(const float4*)(f1 + (size_t)s * 256);
        acc0.x += w0 * p0.x; acc0.y += w0 * p0.y;
        acc0.z += w0 * p0.z; acc0.w += w0 * p0.w;
        acc1.x += w1 * p1.x; acc1.y += w1 * p1.y;
        acc1.z += w1 * p1.z; acc1.w += w1 * p1.w;
    }

    float4 b0 = *(const float4*)(bias + lane * 4);
    float4 b1 = *(const float4*)(bias + 128 + lane * 4);
    float vv0[4] = {acc0.x + b0.x, acc0.y + b0.y, acc0.z + b0.z, acc0.w + b0.w};
    float vv1[4] = {acc1.x + b1.x, acc1.y + b1.y, acc1.z + b1.z, acc1.w + b1.w};
    ushort4 hv0, lv0, hv1, lv1;
    unsigned short *hp0 = &hv0.x, *lp0 = &lv0.x, *hp1 = &hv1.x, *lp1 = &lv1.x;
#pragma unroll
    for (int q = 0; q < 4; q++) {
        float e0 = vv0[q] > 0.f ? vv0[q] : expm1f(vv0[q]);
        __nv_bfloat16 hb = __float2bfloat16(e0);
        hp0[q] = __bfloat16_as_ushort(hb);
        lp0[q] = __bfloat16_as_ushort(__float2bfloat16(e0 - __bfloat162float(hb)));
        float e1 = vv1[q] > 0.f ? vv1[q] : expm1f(vv1[q]);
        hb = __float2bfloat16(e1);
        hp1[q] = __bfloat16_as_ushort(hb);
        lp1[q] = __bfloat16_as_ushort(__float2bfloat16(e1 - __bfloat162float(hb)));
    }
    size_t idx = (size_t)n * 256 + lane * 4;
    *(ushort4*)&ohi[idx] = hv0;
    *(ushort4*)&olo[idx] = lv0;
    *(ushort4*)&ohi[idx + 128] = hv1;
    *(ushort4*)&olo[idx + 128] = lv1;
}

// ---------------------------------------------------------------------------
// layer-2 agg: warp per node, heads on half-warps, online softmax stats
// ---------------------------------------------------------------------------
__global__ void agg2_kernel(const int* __restrict__ off, const int* __restrict__ csr,
                            const float* __restrict__ asrc, const float* __restrict__ adst,
                            const float* __restrict__ feat,
                            const float* __restrict__ bmu, const float* __restrict__ bls,
                            float* __restrict__ out, long headStride, int Nn)
{
    int warpi = (blockIdx.x * blockDim.x + threadIdx.x) >> 5;
    int lane = threadIdx.x & 31;
    if (warpi >= Nn) return;
    int n = warpi;
    int h = lane >> 4, l = lane & 15;
    int o0 = off[n], o1 = off[n + 1];
    float ad = adst[n * 2 + h];

    float m = -1e30f, den = 0.f;
    for (int j = o0 + l; j < o1; j += 16) {
        float e = lrelu(asrc[csr[j] * 2 + h] + ad);
        float nm = fmaxf(m, e);
        den = den * __expf(m - nm) + __expf(e - nm);
        m = nm;
    }
#pragma unroll
    for (int o = 8; o; o >>= 1) {
        float mo = __shfl_xor_sync(~0u, m, o), dd = __shfl_xor_sync(~0u, den, o);
        float nm = fmaxf(m, mo);
        den = den * __expf(m - nm) + dd * __expf(mo - nm);
        m = nm;
    }
    float inv = 1.f / (den + 1e-16f);

    float4 acc = make_float4(0.f, 0.f, 0.f, 0.f);
    const float* fb = feat + h * 64 + l * 4;
    int j = o0;
    for (; j + 3 < o1; j += 4) {
        int s0 = csr[j], s1 = csr[j + 1], s2 = csr[j + 2], s3 = csr[j + 3];
        float a0 = __expf(lrelu(asrc[s0 * 2 + h] + ad) - m) * inv;
        float a1 = __expf(lrelu(asrc[s1 * 2 + h] + ad) - m) * inv;
        float a2 = __expf(lrelu(asrc[s2 * 2 + h] + ad) - m) * inv;
        float a3 = __expf(lrelu(asrc[s3 * 2 + h] + ad) - m) * inv;
        float4 p0 = *(const float4*)(fb + (size_t)s0 * 128);
        float4 p1 = *(const float4*)(fb + (size_t)s1 * 128);
        float4 p2 = *(const float4*)(fb + (size_t)s2 * 128);
        float4 p3 = *(const float4*)(fb + (size_t)s3 * 128);
        acc.x += a0 * p0.x + a1 * p1.x + a2 * p2.x + a3 * p3.x;
        acc.y += a0 * p0.y + a1 * p1.y + a2 * p2.y + a3 * p3.y;
        acc.z += a0 * p0.z + a1 * p1.z + a2 * p2.z + a3 * p3.z;
        acc.w += a0 * p0.w + a1 * p1.w + a2 * p2.w + a3 * p3.w;
    }
    for (; j < o1; j++) {
        int s = csr[j];
        float a = __expf(lrelu(asrc[s * 2 + h] + ad) - m) * inv;
        float4 p = *(const float4*)(fb + (size_t)s * 128);
        acc.x += a * p.x; acc.y += a * p.y; acc.z += a * p.z; acc.w += a * p.w;
    }

    float4 b4 = *(const float4*)((h ? bls : bmu) + l * 4);
    acc.x += b4.x; acc.y += b4.y; acc.z += b4.z; acc.w += b4.w;
    *(float4*)&out[(size_t)h * headStride + (size_t)n * 64 + l * 4] = acc;
}

// ---------------------------------------------------------------------------
static inline int cdiv(long a, int b) { return (int)((a + b - 1) / b); }

extern "C" void kernel_launch(void* const* d_in, const int* in_sizes, int n_in,
                              void* d_out, int out_size)
{
    const float* x          = (const float*)d_in[0];
    const int*   edge_index = (const int*)d_in[1];
    const float* W1         = (const float*)d_in[2];
    const float* att_src1   = (const float*)d_in[3];
    const float* att_dst1   = (const float*)d_in[4];
    const float* b1         = (const float*)d_in[5];
    const float* W_mu       = (const float*)d_in[6];
    const float* att_src_mu = (const float*)d_in[7];
    const float* att_dst_mu = (const float*)d_in[8];
    const float* b_mu       = (const float*)d_in[9];
    const float* W_ls       = (const float*)d_in[10];
    const float* att_src_ls = (const float*)d_in[11];
    const float* att_dst_ls = (const float*)d_in[12];
    const float* b_ls       = (const float*)d_in[13];
    float* out = (float*)d_out;

    const int N  = in_sizes[0] / 128;
    const int nE = in_sizes[1] / 2;
    const int nTot = nE + N;

    float *p_h1, *p_h2, *p_as1, *p_ad1, *p_as2, *p_ad2;
    int *p_deg, *p_off, *p_cur, *p_csr;
    __nv_bfloat16 *p_xhi, *p_xlo, *p_a2hi, *p_a2lo, *p_w1hi, *p_w1lo, *p_w2hi, *p_w2lo;
    cudaGetSymbolAddress((void**)&p_h1,   g_h1);
    cudaGetSymbolAddress((void**)&p_h2,   g_h2);
    cudaGetSymbolAddress((void**)&p_as1,  g_asrc1);
    cudaGetSymbolAddress((void**)&p_ad1,  g_adst1);
    cudaGetSymbolAddress((void**)&p_as2,  g_asrc2);
    cudaGetSymbolAddress((void**)&p_ad2,  g_adst2);
    cudaGetSymbolAddress((void**)&p_deg,  g_deg);
    cudaGetSymbolAddress((void**)&p_off,  g_off);
    cudaGetSymbolAddress((void**)&p_cur,  g_cur);
    cudaGetSymbolAddress((void**)&p_csr,  g_csr);
    cudaGetSymbolAddress((void**)&p_xhi,  g_xhi);
    cudaGetSymbolAddress((void**)&p_xlo,  g_xlo);
    cudaGetSymbolAddress((void**)&p_a2hi, g_a2hi);
    cudaGetSymbolAddress((void**)&p_a2lo, g_a2lo);
    cudaGetSymbolAddress((void**)&p_w1hi, g_w1hi);
    cudaGetSymbolAddress((void**)&p_w1lo, g_w1lo);
    cudaGetSymbolAddress((void**)&p_w2hi, g_w2hi);
    cudaGetSymbolAddress((void**)&p_w2lo, g_w2lo);

    cudaFuncSetAttribute(gemm_bf16_kernel,
                         cudaFuncAttributeMaxDynamicSharedMemorySize, GEMM_SMEM);

    const int T = 256;

    // Reordered launches (dependency-equivalent; single in-order stream):
    // puts gemm1 on the launch index ncu's `-s 5 -c 1` captures, so the
    // profile finally shows GEMM (or agg) stats instead of scatter.
    // 1) zero deg + att-scalar buffers
    zero_all_kernel<<<cdiv(N, T), T>>>(p_deg, p_as1, p_ad1, p_as2, p_ad2, N);
    // 2) edge histogram (needs zero only)
    hist_kernel<<<cdiv(nTot, T), T>>>(edge_index, nE, nTot, p_deg);
    // 3) operand conversion (independent of CSR)
    {
        long total = (long)N * 128 + 256 * 128 + 128 * 256;
        cvt_all_kernel<<<cdiv(total, T), T>>>(x, W1, W_mu, W_ls,
            p_xhi, p_xlo, p_w1hi, p_w1lo, p_w2hi, p_w2lo, N * 128);
    }
    // 4) layer-1 GEMM + fused att scalars (needs cvt + zero; NOT CSR)
    {
        dim3 grid(2, cdiv(N, 128));
        gemm_bf16_kernel<<<grid, 256, GEMM_SMEM>>>(
            p_xhi, p_xlo, p_w1hi, p_w1lo, p_h1, N, 128, 256,
            att_src1, att_src1 + 128, att_dst1, att_dst1 + 128, 7, p_as1, p_ad1);
    }
    // 5) CSR scan (needs hist)
    scan_kernel<<<1, 1024>>>(p_deg, p_off, p_cur, N);
    // 6) CSR scatter (needs scan)
    scatter_kernel<<<cdiv(nTot, T), T>>>(edge_index, nE, nTot, p_cur, p_csr);
    // 7) layer-1 aggregation (needs scatter + gemm1)
    agg1_kernel<<<cdiv((long)N * 32, T), T>>>(
        p_off, p_csr, p_as1, p_ad1, p_h1, b1, p_a2hi, p_a2lo, N);
    // 8) layer-2 GEMM + fused att scalars
    {
        dim3 grid(1, cdiv(N, 128));
        gemm_bf16_kernel<<<grid, 256, GEMM_SMEM>>>(
            p_a2hi, p_a2lo, p_w2hi, p_w2lo, p_h2, N, 256, 128,
            att_src_mu, att_src_ls, att_dst_mu, att_dst_ls, 6, p_as2, p_ad2);
    }
    // 9) layer-2 aggregation -> output
    agg2_kernel<<<cdiv((long)N * 32, T), T>>>(
        p_off, p_csr, p_as2, p_ad2, p_h2, b_mu, b_ls, out, (long)N * 64, N);
}

// round 15
// speedup vs baseline: 1.5118x; 1.0006x over previous
#include <cuda_runtime.h>
#include <cuda_bf16.h>
#include <cstdint>
#include <stdint.h>
#include <math.h>

#define MAX_N 50000
#define MAX_E 400000
#define MAX_ETOT (MAX_N + MAX_E)
#define NEG_SLOPE 0.2f
#define NPAD (MAX_N + 128)

// ---------------- scratch (device globals, allocation-free) ----------------
__device__ float g_h1[MAX_N * 256];    // conv1 features  [N,2,128]
__device__ float g_h2[MAX_N * 128];    // layer2 feats    [N,{mu,ls},64]
__device__ float g_asrc1[MAX_N * 2];
__device__ float g_adst1[MAX_N * 2];
__device__ float g_asrc2[MAX_N * 2];
__device__ float g_adst2[MAX_N * 2];
__device__ int   g_deg[MAX_N];
__device__ int   g_off[MAX_N + 1];
__device__ int   g_cur[MAX_N];
__device__ int   g_csr[MAX_ETOT];      // src node per CSR slot (sorted by dst)

// bf16 hi/lo operand arrays (zero-initialized; padding rows stay 0)
__device__ __nv_bfloat16 g_xhi[NPAD * 128],  g_xlo[NPAD * 128];   // layer1 A
__device__ __nv_bfloat16 g_a2hi[NPAD * 256], g_a2lo[NPAD * 256];  // layer2 A (ELU out)
__device__ __nv_bfloat16 g_w1hi[256 * 128],  g_w1lo[256 * 128];   // layer1 B  [n][k]
__device__ __nv_bfloat16 g_w2hi[128 * 256],  g_w2lo[128 * 256];   // layer2 B  [n][k]

// ======================= PTX helpers ======================================
__device__ __forceinline__ uint32_t smem_u32(const void* p) {
    uint32_t a;
    asm("{ .reg .u64 t; cvta.to.shared.u64 t, %1; cvt.u32.u64 %0, t; }"
        : "=r"(a) : "l"(p));
    return a;
}

#define CP16(saddr, gptr) \
    asm volatile("cp.async.cg.shared.global [%0], [%1], 16;" \
                 :: "r"(saddr), "l"(gptr) : "memory")
#define CP_COMMIT() asm volatile("cp.async.commit_group;" ::: "memory")
#define CP_WAIT0()  asm volatile("cp.async.wait_group 0;" ::: "memory")
#define CP_WAIT1()  asm volatile("cp.async.wait_group 1;" ::: "memory")

#define LDSM4(r0, r1, r2, r3, addr)                                            \
    asm volatile("ldmatrix.sync.aligned.m8n8.x4.shared.b16 {%0,%1,%2,%3}, [%4];" \
                 : "=r"(r0), "=r"(r1), "=r"(r2), "=r"(r3) : "r"(addr))

#define MMA_OP(c, a, b)                                                        \
    asm volatile(                                                              \
        "mma.sync.aligned.m16n8k16.row.col.f32.bf16.bf16.f32 "                 \
        "{%0,%1,%2,%3}, {%4,%5,%6,%7}, {%8,%9}, {%0,%1,%2,%3};"                \
        : "+f"((c)[0]), "+f"((c)[1]), "+f"((c)[2]), "+f"((c)[3])               \
        : "r"((a)[0]), "r"((a)[1]), "r"((a)[2]), "r"((a)[3]),                  \
          "r"((b)[0]), "r"((b)[1]))

// smem tile geometry: 128 rows x 32 k, row stride 40 bf16 (80 B, LDSM-clean)
#define TROW 40
#define TELEM (128 * TROW)
#define STAGE_ELEM (4 * TELEM)
#define GEMM_SMEM (2 * STAGE_ELEM * 2)

// ===========================================================================
// bf16 hi/lo split GEMM + fused attention-scalar epilogue
// ===========================================================================
__global__ __launch_bounds__(256) void gemm_bf16_kernel(
    const __nv_bfloat16* __restrict__ Ahi, const __nv_bfloat16* __restrict__ Alo,
    const __nv_bfloat16* __restrict__ Bhi, const __nv_bfloat16* __restrict__ Blo,
    float* __restrict__ C, int M, int KTOT, int ldc,
    const float* __restrict__ attS0, const float* __restrict__ attS1,
    const float* __restrict__ attD0, const float* __restrict__ attD1,
    int hshift, float* __restrict__ asrc, float* __restrict__ adst)
{
    extern __shared__ __nv_bfloat16 sm[];
    const uint32_t sbase = smem_u32(sm);

    const int tid = threadIdx.x, warp = tid >> 5, lane = tid & 31;
    const int wm = warp & 1, wn = warp >> 1;
    const int row0 = blockIdx.y * 128;
    const int col0 = blockIdx.x * 128;
    const int nch = KTOT >> 5;

    float acc[4][4][4];
#pragma unroll
    for (int mt = 0; mt < 4; mt++)
#pragma unroll
        for (int nt = 0; nt < 4; nt++)
#pragma unroll
            for (int i = 0; i < 4; i++) acc[mt][nt][i] = 0.f;

    auto issue = [&](int stage, int kb) {
        const int so = stage * STAGE_ELEM;
#pragma unroll
        for (int it = 0; it < 2; it++) {
            int vec = tid + it * 256;
            int m = vec >> 2, ko = (vec & 3) * 8;
            uint32_t sd = sbase + (uint32_t)(so + m * TROW + ko) * 2;
            size_t ga = (size_t)(row0 + m) * KTOT + kb + ko;
            CP16(sd,             Ahi + ga);
            CP16(sd + TELEM * 2, Alo + ga);
            size_t gb = (size_t)(col0 + m) * KTOT + kb + ko;
            CP16(sd + TELEM * 4, Bhi + gb);
            CP16(sd + TELEM * 6, Blo + gb);
        }
        CP_COMMIT();
    };

    issue(0, 0);

    const int arow = wm * 64 + (lane & 15);
    const int acol = (lane >> 4) * 8;
    const int bmid = lane >> 3, brin = lane & 7;

    for (int c = 0; c < nch; c++) {
        if (c + 1 < nch) { issue((c + 1) & 1, (c + 1) * 32); CP_WAIT1(); }
        else             { CP_WAIT0(); }
        __syncthreads();

        const uint32_t aAh = sbase + (uint32_t)((c & 1) * STAGE_ELEM) * 2;
        const uint32_t aAl = aAh + TELEM * 2;
        const uint32_t aBh = aAh + TELEM * 4;
        const uint32_t aBl = aAh + TELEM * 6;

#pragma unroll
        for (int ks = 0; ks < 2; ks++) {
            const int k0 = ks * 16;
            uint32_t ah[4][4], al[4][4];
#pragma unroll
            for (int mt = 0; mt < 4; mt++) {
                uint32_t off = (uint32_t)((arow + mt * 16) * TROW + k0 + acol) * 2;
                LDSM4(ah[mt][0], ah[mt][1], ah[mt][2], ah[mt][3], aAh + off);
                LDSM4(al[mt][0], al[mt][1], al[mt][2], al[mt][3], aAl + off);
            }
            uint32_t bh[4][2], bl[4][2];
#pragma unroll
            for (int p = 0; p < 2; p++) {
                int bn = wn * 32 + p * 16 + (bmid >> 1) * 8 + brin;
                int bc = k0 + (bmid & 1) * 8;
                uint32_t off = (uint32_t)(bn * TROW + bc) * 2;
                uint32_t r0, r1, r2, r3;
                LDSM4(r0, r1, r2, r3, aBh + off);
                bh[p * 2][0] = r0; bh[p * 2][1] = r1;
                bh[p * 2 + 1][0] = r2; bh[p * 2 + 1][1] = r3;
                LDSM4(r0, r1, r2, r3, aBl + off);
                bl[p * 2][0] = r0; bl[p * 2][1] = r1;
                bl[p * 2 + 1][0] = r2; bl[p * 2 + 1][1] = r3;
            }
#pragma unroll
            for (int mt = 0; mt < 4; mt++)
#pragma unroll
                for (int nt = 0; nt < 4; nt++) {
                    MMA_OP(acc[mt][nt], ah[mt], bh[nt]);
                    MMA_OP(acc[mt][nt], ah[mt], bl[nt]);
                    MMA_OP(acc[mt][nt], al[mt], bh[nt]);
                }
        }
        __syncthreads();
    }

    const int qrow = lane >> 2, qcol = (lane & 3) * 2;

#pragma unroll
    for (int mt = 0; mt < 4; mt++) {
#pragma unroll
        for (int nt = 0; nt < 4; nt++) {
            int r = row0 + wm * 64 + mt * 16 + qrow;
            int cc = col0 + wn * 32 + nt * 8 + qcol;
            if (r < M)
                *(float2*)&C[(size_t)r * ldc + cc] =
                    make_float2(acc[mt][nt][0], acc[mt][nt][1]);
            if (r + 8 < M)
                *(float2*)&C[(size_t)(r + 8) * ldc + cc] =
                    make_float2(acc[mt][nt][2], acc[mt][nt][3]);
        }
    }

    // ---- fused attention scalars
    const int hmask = (1 << hshift) - 1;
    const int h = (col0 + wn * 32) >> hshift;
    const float* aS = h ? attS1 : attS0;
    const float* aD = h ? attD1 : attD0;
    float ws[4][2], wd[4][2];
#pragma unroll
    for (int nt = 0; nt < 4; nt++) {
        int ci = (col0 + wn * 32 + nt * 8 + qcol) & hmask;
        ws[nt][0] = aS[ci];     ws[nt][1] = aS[ci + 1];
        wd[nt][0] = aD[ci];     wd[nt][1] = aD[ci + 1];
    }
#pragma unroll
    for (int mt = 0; mt < 4; mt++) {
        float slo = 0.f, shi = 0.f, dlo = 0.f, dhi = 0.f;
#pragma unroll
        for (int nt = 0; nt < 4; nt++) {
            slo += acc[mt][nt][0] * ws[nt][0] + acc[mt][nt][1] * ws[nt][1];
            shi += acc[mt][nt][2] * ws[nt][0] + acc[mt][nt][3] * ws[nt][1];
            dlo += acc[mt][nt][0] * wd[nt][0] + acc[mt][nt][1] * wd[nt][1];
            dhi += acc[mt][nt][2] * wd[nt][0] + acc[mt][nt][3] * wd[nt][1];
        }
#pragma unroll
        for (int o = 1; o <= 2; o <<= 1) {
            slo += __shfl_xor_sync(~0u, slo, o);
            shi += __shfl_xor_sync(~0u, shi, o);
            dlo += __shfl_xor_sync(~0u, dlo, o);
            dhi += __shfl_xor_sync(~0u, dhi, o);
        }
        if ((lane & 3) == 0) {
            int r = row0 + wm * 64 + mt * 16 + qrow;
            if (r < M) {
                atomicAdd(&asrc[r * 2 + h], slo);
                atomicAdd(&adst[r * 2 + h], dlo);
            }
            if (r + 8 < M) {
                atomicAdd(&asrc[(r + 8) * 2 + h], shi);
                atomicAdd(&adst[(r + 8) * 2 + h], dhi);
            }
        }
    }
}

// ---------------------------------------------------------------------------
__global__ void zero_all_kernel(int* __restrict__ deg,
                                float* __restrict__ a1, float* __restrict__ d1,
                                float* __restrict__ a2, float* __restrict__ d2,
                                int N)
{
    int i = blockIdx.x * blockDim.x + threadIdx.x;
    if (i >= N) return;
    deg[i] = 0;
    float2 z = make_float2(0.f, 0.f);
    *(float2*)&a1[i * 2] = z;
    *(float2*)&d1[i * 2] = z;
    *(float2*)&a2[i * 2] = z;
    *(float2*)&d2[i * 2] = z;
}

__global__ void cvt_all_kernel(const float* __restrict__ x,
                               const float* __restrict__ W1,
                               const float* __restrict__ Wmu,
                               const float* __restrict__ Wls,
                               __nv_bfloat16* __restrict__ xhi,
                               __nv_bfloat16* __restrict__ xlo,
                               __nv_bfloat16* __restrict__ w1hi,
                               __nv_bfloat16* __restrict__ w1lo,
                               __nv_bfloat16* __restrict__ w2hi,
                               __nv_bfloat16* __restrict__ w2lo,
                               int nx)
{
    int i = blockIdx.x * blockDim.x + threadIdx.x;
    float v;
    __nv_bfloat16* hi;
    __nv_bfloat16* lo;
    int o;
    if (i < nx) {
        v = x[i]; hi = xhi; lo = xlo; o = i;
    } else if (i < nx + 256 * 128) {
        o = i - nx;
        int n = o >> 7, k = o & 127;
        v = W1[k * 256 + n]; hi = w1hi; lo = w1lo;
    } else if (i < nx + 256 * 128 + 128 * 256) {
        o = i - nx - 256 * 128;
        int n = o >> 8, k = o & 255;
        v = (n < 64) ? Wmu[k * 64 + n] : Wls[k * 64 + n - 64];
        hi = w2hi; lo = w2lo;
    } else return;
    __nv_bfloat16 h = __float2bfloat16(v);
    hi[o] = h;
    lo[o] = __float2bfloat16(v - __bfloat162float(h));
}

// ---------------------------------------------------------------------------
// CSR build
// ---------------------------------------------------------------------------
__global__ void hist_kernel(const int* __restrict__ ei, int nE, int nTot,
                            int* __restrict__ deg)
{
    int e = blockIdx.x * blockDim.x + threadIdx.x;
    if (e >= nTot) return;
    int d = (e < nE) ? ei[nE + e] : e - nE;
    atomicAdd(&deg[d], 1);
}

__global__ __launch_bounds__(1024) void scan_kernel(
    const int* __restrict__ deg, int* __restrict__ off,
    int* __restrict__ cur, int N)
{
    __shared__ int ssum[1024];
    int tid = threadIdx.x;
    int chunk = (N + 1023) / 1024;
    int start = tid * chunk;
    int end = min(start + chunk, N);
    int s = 0;
    for (int i = start; i < end; i++) s += deg[i];
    ssum[tid] = s;
    __syncthreads();
    for (int o = 1; o < 1024; o <<= 1) {
        int v = 0;
        if (tid >= o) v = ssum[tid - o];
        __syncthreads();
        if (tid >= o) ssum[tid] += v;
        __syncthreads();
    }
    int base = (tid > 0) ? ssum[tid - 1] : 0;
    for (int i = start; i < end; i++) {
        off[i] = base;
        cur[i] = base;
        base += deg[i];
    }
    if (tid == 1023) off[N] = ssum[1023];
}

__global__ void scatter_kernel(const int* __restrict__ ei, int nE, int nTot,
                               int* __restrict__ cur, int* __restrict__ csr)
{
    int e = blockIdx.x * blockDim.x + threadIdx.x;
    if (e >= nTot) return;
    int s, d;
    if (e < nE) { s = ei[e]; d = ei[nE + e]; }
    else        { s = e - nE; d = s; }
    int pos = atomicAdd(&cur[d], 1);
    csr[pos] = s;
}

// ---------------------------------------------------------------------------
__device__ __forceinline__ float lrelu(float v) { return v > 0.f ? v : NEG_SLOPE * v; }

// ---------------------------------------------------------------------------
// layer-1 agg: warp per node, both heads; online softmax;
// gather unrolled 4 edges x 2 heads (8 independent float4 loads in flight)
// ---------------------------------------------------------------------------
__global__ void agg1_kernel(const int* __restrict__ off, const int* __restrict__ csr,
                            const float* __restrict__ asrc, const float* __restrict__ adst,
                            const float* __restrict__ feat, const float* __restrict__ bias,
                            __nv_bfloat16* __restrict__ ohi,
                            __nv_bfloat16* __restrict__ olo, int Nn)
{
    int warpi = (blockIdx.x * blockDim.x + threadIdx.x) >> 5;
    int lane = threadIdx.x & 31;
    if (warpi >= Nn) return;
    int n = warpi;
    int o0 = off[n], o1 = off[n + 1];
    float2 adv = *(const float2*)&adst[n * 2];

    float m0 = -1e30f, d0 = 0.f, m1 = -1e30f, d1 = 0.f;
    for (int j = o0 + lane; j < o1; j += 32) {
        float2 a = *(const float2*)&asrc[csr[j] * 2];
        float e0 = lrelu(a.x + adv.x);
        float e1 = lrelu(a.y + adv.y);
        float nm0 = fmaxf(m0, e0);
        d0 = d0 * __expf(m0 - nm0) + __expf(e0 - nm0);
        m0 = nm0;
        float nm1 = fmaxf(m1, e1);
        d1 = d1 * __expf(m1 - nm1) + __expf(e1 - nm1);
        m1 = nm1;
    }
#pragma unroll
    for (int o = 16; o; o >>= 1) {
        float mo = __shfl_xor_sync(~0u, m0, o), dd = __shfl_xor_sync(~0u, d0, o);
        float nm = fmaxf(m0, mo);
        d0 = d0 * __expf(m0 - nm) + dd * __expf(mo - nm);
        m0 = nm;
        mo = __shfl_xor_sync(~0u, m1, o); dd = __shfl_xor_sync(~0u, d1, o);
        nm = fmaxf(m1, mo);
        d1 = d1 * __expf(m1 - nm) + dd * __expf(mo - nm);
        m1 = nm;
    }
    float inv0 = 1.f / (d0 + 1e-16f);
    float inv1 = 1.f / (d1 + 1e-16f);

    const float* f0 = feat + lane * 4;
    const float* f1 = feat + 128 + lane * 4;
    float4 acc0 = make_float4(0.f, 0.f, 0.f, 0.f);
    float4 acc1 = make_float4(0.f, 0.f, 0.f, 0.f);
    int j = o0;
    // unroll 4 edges x 2 heads -> 8 independent float4 loads in flight
    for (; j + 3 < o1; j += 4) {
        int s0 = csr[j], s1 = csr[j + 1], s2 = csr[j + 2], s3 = csr[j + 3];
        float2 a0 = *(const float2*)&asrc[s0 * 2];
        float2 a1 = *(const float2*)&asrc[s1 * 2];
        float2 a2 = *(const float2*)&asrc[s2 * 2];
        float2 a3 = *(const float2*)&asrc[s3 * 2];
        float4 p00 = *(const float4*)(f0 + (size_t)s0 * 256);
        float4 p01 = *(const float4*)(f1 + (size_t)s0 * 256);
        float4 p10 = *(const float4*)(f0 + (size_t)s1 * 256);
        float4 p11 = *(const float4*)(f1 + (size_t)s1 * 256);
        float4 p20 = *(const float4*)(f0 + (size_t)s2 * 256);
        float4 p21 = *(const float4*)(f1 + (size_t)s2 * 256);
        float4 p30 = *(const float4*)(f0 + (size_t)s3 * 256);
        float4 p31 = *(const float4*)(f1 + (size_t)s3 * 256);
        float w00 = __expf(lrelu(a0.x + adv.x) - m0) * inv0;
        float w01 = __expf(lrelu(a0.y + adv.y) - m1) * inv1;
        float w10 = __expf(lrelu(a1.x + adv.x) - m0) * inv0;
        float w11 = __expf(lrelu(a1.y + adv.y) - m1) * inv1;
        float w20 = __expf(lrelu(a2.x + adv.x) - m0) * inv0;
        float w21 = __expf(lrelu(a2.y + adv.y) - m1) * inv1;
        float w30 = __expf(lrelu(a3.x + adv.x) - m0) * inv0;
        float w31 = __expf(lrelu(a3.y + adv.y) - m1) * inv1;
        acc0.x += w00 * p00.x + w10 * p10.x + w20 * p20.x + w30 * p30.x;
        acc0.y += w00 * p00.y + w10 * p10.y + w20 * p20.y + w30 * p30.y;
        acc0.z += w00 * p00.z + w10 * p10.z + w20 * p20.z + w30 * p30.z;
        acc0.w += w00 * p00.w + w10 * p10.w + w20 * p20.w + w30 * p30.w;
        acc1.x += w01 * p01.x + w11 * p11.x + w21 * p21.x + w31 * p31.x;
        acc1.y += w01 * p01.y + w11 * p11.y + w21 * p21.y + w31 * p31.y;
        acc1.z += w01 * p01.z + w11 * p11.z + w21 * p21.z + w31 * p31.z;
        acc1.w += w01 * p01.w + w11 * p11.w + w21 * p21.w + w31 * p31.w;
    }
    for (; j < o1; j++) {
        int s = csr[j];
        float2 a = *(const float2*)&asrc[s * 2];
        float w0 = __expf(lrelu(a.x + adv.x) - m0) * inv0;
        float w1 = __expf(lrelu(a.y + adv.y) - m1) * inv1;
        float4 p0 = *(const float4*)(f0 + (size_t)s * 256);
        float4 p1 = *(const float4*)(f1 + (size_t)s * 256);
        acc0.x += w0 * p0.x; acc0.y += w0 * p0.y;
        acc0.z += w0 * p0.z; acc0.w += w0 * p0.w;
        acc1.x += w1 * p1.x; acc1.y += w1 * p1.y;
        acc1.z += w1 * p1.z; acc1.w += w1 * p1.w;
    }

    float4 b0 = *(const float4*)(bias + lane * 4);
    float4 b1 = *(const float4*)(bias + 128 + lane * 4);
    float vv0[4] = {acc0.x + b0.x, acc0.y + b0.y, acc0.z + b0.z, acc0.w + b0.w};
    float vv1[4] = {acc1.x + b1.x, acc1.y + b1.y, acc1.z + b1.z, acc1.w + b1.w};
    ushort4 hv0, lv0, hv1, lv1;
    unsigned short *hp0 = &hv0.x, *lp0 = &lv0.x, *hp1 = &hv1.x, *lp1 = &lv1.x;
#pragma unroll
    for (int q = 0; q < 4; q++) {
        float e0 = vv0[q] > 0.f ? vv0[q] : expm1f(vv0[q]);
        __nv_bfloat16 hb = __float2bfloat16(e0);
        hp0[q] = __bfloat16_as_ushort(hb);
        lp0[q] = __bfloat16_as_ushort(__float2bfloat16(e0 - __bfloat162float(hb)));
        float e1 = vv1[q] > 0.f ? vv1[q] : expm1f(vv1[q]);
        hb = __float2bfloat16(e1);
        hp1[q] = __bfloat16_as_ushort(hb);
        lp1[q] = __bfloat16_as_ushort(__float2bfloat16(e1 - __bfloat162float(hb)));
    }
    size_t idx = (size_t)n * 256 + lane * 4;
    *(ushort4*)&ohi[idx] = hv0;
    *(ushort4*)&olo[idx] = lv0;
    *(ushort4*)&ohi[idx + 128] = hv1;
    *(ushort4*)&olo[idx + 128] = lv1;
}

// ---------------------------------------------------------------------------
// layer-2 agg: warp per node, heads on half-warps, online softmax stats
// ---------------------------------------------------------------------------
__global__ void agg2_kernel(const int* __restrict__ off, const int* __restrict__ csr,
                            const float* __restrict__ asrc, const float* __restrict__ adst,
                            const float* __restrict__ feat,
                            const float* __restrict__ bmu, const float* __restrict__ bls,
                            float* __restrict__ out, long headStride, int Nn)
{
    int warpi = (blockIdx.x * blockDim.x + threadIdx.x) >> 5;
    int lane = threadIdx.x & 31;
    if (warpi >= Nn) return;
    int n = warpi;
    int h = lane >> 4, l = lane & 15;
    int o0 = off[n], o1 = off[n + 1];
    float ad = adst[n * 2 + h];

    float m = -1e30f, den = 0.f;
    for (int j = o0 + l; j < o1; j += 16) {
        float e = lrelu(asrc[csr[j] * 2 + h] + ad);
        float nm = fmaxf(m, e);
        den = den * __expf(m - nm) + __expf(e - nm);
        m = nm;
    }
#pragma unroll
    for (int o = 8; o; o >>= 1) {
        float mo = __shfl_xor_sync(~0u, m, o), dd = __shfl_xor_sync(~0u, den, o);
        float nm = fmaxf(m, mo);
        den = den * __expf(m - nm) + dd * __expf(mo - nm);
        m = nm;
    }
    float inv = 1.f / (den + 1e-16f);

    float4 acc = make_float4(0.f, 0.f, 0.f, 0.f);
    const float* fb = feat + h * 64 + l * 4;
    int j = o0;
    for (; j + 3 < o1; j += 4) {
        int s0 = csr[j], s1 = csr[j + 1], s2 = csr[j + 2], s3 = csr[j + 3];
        float a0 = __expf(lrelu(asrc[s0 * 2 + h] + ad) - m) * inv;
        float a1 = __expf(lrelu(asrc[s1 * 2 + h] + ad) - m) * inv;
        float a2 = __expf(lrelu(asrc[s2 * 2 + h] + ad) - m) * inv;
        float a3 = __expf(lrelu(asrc[s3 * 2 + h] + ad) - m) * inv;
        float4 p0 = *(const float4*)(fb + (size_t)s0 * 128);
        float4 p1 = *(const float4*)(fb + (size_t)s1 * 128);
        float4 p2 = *(const float4*)(fb + (size_t)s2 * 128);
        float4 p3 = *(const float4*)(fb + (size_t)s3 * 128);
        acc.x += a0 * p0.x + a1 * p1.x + a2 * p2.x + a3 * p3.x;
        acc.y += a0 * p0.y + a1 * p1.y + a2 * p2.y + a3 * p3.y;
        acc.z += a0 * p0.z + a1 * p1.z + a2 * p2.z + a3 * p3.z;
        acc.w += a0 * p0.w + a1 * p1.w + a2 * p2.w + a3 * p3.w;
    }
    for (; j < o1; j++) {
        int s = csr[j];
        float a = __expf(lrelu(asrc[s * 2 + h] + ad) - m) * inv;
        float4 p = *(const float4*)(fb + (size_t)s * 128);
        acc.x += a * p.x; acc.y += a * p.y; acc.z += a * p.z; acc.w += a * p.w;
    }

    float4 b4 = *(const float4*)((h ? bls : bmu) + l * 4);
    acc.x += b4.x; acc.y += b4.y; acc.z += b4.z; acc.w += b4.w;
    *(float4*)&out[(size_t)h * headStride + (size_t)n * 64 + l * 4] = acc;
}

// ---------------------------------------------------------------------------
static inline int cdiv(long a, int b) { return (int)((a + b - 1) / b); }

extern "C" void kernel_launch(void* const* d_in, const int* in_sizes, int n_in,
                              void* d_out, int out_size)
{
    const float* x          = (const float*)d_in[0];
    const int*   edge_index = (const int*)d_in[1];
    const float* W1         = (const float*)d_in[2];
    const float* att_src1   = (const float*)d_in[3];
    const float* att_dst1   = (const float*)d_in[4];
    const float* b1         = (const float*)d_in[5];
    const float* W_mu       = (const float*)d_in[6];
    const float* att_src_mu = (const float*)d_in[7];
    const float* att_dst_mu = (const float*)d_in[8];
    const float* b_mu       = (const float*)d_in[9];
    const float* W_ls       = (const float*)d_in[10];
    const float* att_src_ls = (const float*)d_in[11];
    const float* att_dst_ls = (const float*)d_in[12];
    const float* b_ls       = (const float*)d_in[13];
    float* out = (float*)d_out;

    const int N  = in_sizes[0] / 128;
    const int nE = in_sizes[1] / 2;
    const int nTot = nE + N;

    float *p_h1, *p_h2, *p_as1, *p_ad1, *p_as2, *p_ad2;
    int *p_deg, *p_off, *p_cur, *p_csr;
    __nv_bfloat16 *p_xhi, *p_xlo, *p_a2hi, *p_a2lo, *p_w1hi, *p_w1lo, *p_w2hi, *p_w2lo;
    cudaGetSymbolAddress((void**)&p_h1,   g_h1);
    cudaGetSymbolAddress((void**)&p_h2,   g_h2);
    cudaGetSymbolAddress((void**)&p_as1,  g_asrc1);
    cudaGetSymbolAddress((void**)&p_ad1,  g_adst1);
    cudaGetSymbolAddress((void**)&p_as2,  g_asrc2);
    cudaGetSymbolAddress((void**)&p_ad2,  g_adst2);
    cudaGetSymbolAddress((void**)&p_deg,  g_deg);
    cudaGetSymbolAddress((void**)&p_off,  g_off);
    cudaGetSymbolAddress((void**)&p_cur,  g_cur);
    cudaGetSymbolAddress((void**)&p_csr,  g_csr);
    cudaGetSymbolAddress((void**)&p_xhi,  g_xhi);
    cudaGetSymbolAddress((void**)&p_xlo,  g_xlo);
    cudaGetSymbolAddress((void**)&p_a2hi, g_a2hi);
    cudaGetSymbolAddress((void**)&p_a2lo, g_a2lo);
    cudaGetSymbolAddress((void**)&p_w1hi, g_w1hi);
    cudaGetSymbolAddress((void**)&p_w1lo, g_w1lo);
    cudaGetSymbolAddress((void**)&p_w2hi, g_w2hi);
    cudaGetSymbolAddress((void**)&p_w2lo, g_w2lo);

    cudaFuncSetAttribute(gemm_bf16_kernel,
                         cudaFuncAttributeMaxDynamicSharedMemorySize, GEMM_SMEM);

    const int T = 256;

    // (same launch order as R14 — keeps gemm1 under the profiler)
    zero_all_kernel<<<cdiv(N, T), T>>>(p_deg, p_as1, p_ad1, p_as2, p_ad2, N);
    hist_kernel<<<cdiv(nTot, T), T>>>(edge_index, nE, nTot, p_deg);
    {
        long total = (long)N * 128 + 256 * 128 + 128 * 256;
        cvt_all_kernel<<<cdiv(total, T), T>>>(x, W1, W_mu, W_ls,
            p_xhi, p_xlo, p_w1hi, p_w1lo, p_w2hi, p_w2lo, N * 128);
    }
    {
        dim3 grid(2, cdiv(N, 128));
        gemm_bf16_kernel<<<grid, 256, GEMM_SMEM>>>(
            p_xhi, p_xlo, p_w1hi, p_w1lo, p_h1, N, 128, 256,
            att_src1, att_src1 + 128, att_dst1, att_dst1 + 128, 7, p_as1, p_ad1);
    }
    scan_kernel<<<1, 1024>>>(p_deg, p_off, p_cur, N);
    scatter_kernel<<<cdiv(nTot, T), T>>>(edge_index, nE, nTot, p_cur, p_csr);
    agg1_kernel<<<cdiv((long)N * 32, T), T>>>(
        p_off, p_csr, p_as1, p_ad1, p_h1, b1, p_a2hi, p_a2lo, N);
    {
        dim3 grid(1, cdiv(N, 128));
        gemm_bf16_kernel<<<grid, 256, GEMM_SMEM>>>(
            p_a2hi, p_a2lo, p_w2hi, p_w2lo, p_h2, N, 256, 128,
            att_src_mu, att_src_ls, att_dst_mu, att_dst_ls, 6, p_as2, p_ad2);
    }
    agg2_kernel<<<cdiv((long)N * 32, T), T>>>(
        p_off, p_csr, p_as2, p_ad2, p_h2, b_mu, b_ls, out, (long)N * 64, N);
}